// round 6
// baseline (speedup 1.0000x reference)
#include <cuda_runtime.h>
#include <cuda_bf16.h>
#include <cstdint>

#define Bsz 2
#define Ssz 2048
#define Dsz 2048
#define Hn 16
#define DHsz 128
#define Msz (Bsz*Ssz)

typedef __nv_bfloat16 bf16;
typedef __nv_bfloat162 bf162;

__device__ __align__(16) bf16 g_xhi[(size_t)Msz*Dsz], g_xlo[(size_t)Msz*Dsz];
__device__ __align__(16) bf16 g_Whi[4][(size_t)Dsz*Dsz], g_Wlo[4][(size_t)Dsz*Dsz];
__device__ __align__(16) bf16 g_Qhi[(size_t)Msz*Dsz], g_Qlo[(size_t)Msz*Dsz];
__device__ __align__(16) bf16 g_Khi[(size_t)Msz*Dsz], g_Klo[(size_t)Msz*Dsz];
__device__ __align__(16) float g_V[(size_t)Msz*Dsz];
__device__ __align__(16) bf16 g_Ahi[(size_t)Msz*Dsz], g_Alo[(size_t)Msz*Dsz];
__device__ float g_w[Bsz*Hn*Ssz];

__device__ __forceinline__ uint32_t smem_u32(const void* p) {
    uint32_t a;
    asm("{ .reg .u64 t; cvta.to.shared.u64 t, %1; cvt.u32.u64 %0, t; }" : "=r"(a) : "l"(p));
    return a;
}
__device__ __forceinline__ void ldsm4(uint32_t* r, uint32_t a) {
    asm volatile("ldmatrix.sync.aligned.m8n8.x4.shared.b16 {%0,%1,%2,%3}, [%4];"
                 : "=r"(r[0]), "=r"(r[1]), "=r"(r[2]), "=r"(r[3]) : "r"(a));
}
__device__ __forceinline__ void mma16816(float* c, const uint32_t* a, uint32_t b0, uint32_t b1) {
    asm volatile("mma.sync.aligned.m16n8k16.row.col.f32.bf16.bf16.f32 "
                 "{%0,%1,%2,%3},{%4,%5,%6,%7},{%8,%9},{%0,%1,%2,%3};"
                 : "+f"(c[0]), "+f"(c[1]), "+f"(c[2]), "+f"(c[3])
                 : "r"(a[0]), "r"(a[1]), "r"(a[2]), "r"(a[3]), "r"(b0), "r"(b1));
}
#define CP16(dst, src) asm volatile("cp.async.cg.shared.global [%0], [%1], 16;" :: "r"(dst), "l"(src))
#define CP_COMMIT()    asm volatile("cp.async.commit_group;" ::: "memory")
#define CP_WAIT1()     asm volatile("cp.async.wait_group 1;" ::: "memory")
#define CP_WAIT0()     asm volatile("cp.async.wait_group 0;" ::: "memory")

// ---------------- elementwise ----------------
__global__ __launch_bounds__(256) void split_kernel(const float* __restrict__ src, int sel, int n4) {
    int i = blockIdx.x * 256 + threadIdx.x;
    if (i >= n4) return;
    bf16* hi = (sel == 4) ? g_xhi : g_Whi[sel];
    bf16* lo = (sel == 4) ? g_xlo : g_Wlo[sel];
    float4 v = ((const float4*)src)[i];
    bf16 a = __float2bfloat16(v.x), b = __float2bfloat16(v.y);
    bf16 c = __float2bfloat16(v.z), d = __float2bfloat16(v.w);
    bf162 h0{a,b}, h1{c,d};
    ((bf162*)hi)[i*2] = h0; ((bf162*)hi)[i*2+1] = h1;
    bf162 l0{__float2bfloat16(v.x - __bfloat162float(a)), __float2bfloat16(v.y - __bfloat162float(b))};
    bf162 l1{__float2bfloat16(v.z - __bfloat162float(c)), __float2bfloat16(v.w - __bfloat162float(d))};
    ((bf162*)lo)[i*2] = l0; ((bf162*)lo)[i*2+1] = l1;
}

__global__ __launch_bounds__(256) void wvsplit_kernel() {
    int i = blockIdx.x * 256 + threadIdx.x;
    int e = i * 4, m = e >> 11, d = e & 2047;
    float wv = g_w[(((m >> 11) * Hn + (d >> 7)) << 11) + (m & 2047)];
    float4 v = ((const float4*)g_V)[i];
    v.x *= wv; v.y *= wv; v.z *= wv; v.w *= wv;
    bf16 a = __float2bfloat16(v.x), b = __float2bfloat16(v.y);
    bf16 c = __float2bfloat16(v.z), dd = __float2bfloat16(v.w);
    bf162 h0{a,b}, h1{c,dd};
    ((bf162*)g_Ahi)[i*2] = h0; ((bf162*)g_Ahi)[i*2+1] = h1;
    bf162 l0{__float2bfloat16(v.x - __bfloat162float(a)), __float2bfloat16(v.y - __bfloat162float(b))};
    bf162 l1{__float2bfloat16(v.z - __bfloat162float(c)), __float2bfloat16(v.w - __bfloat162float(dd))};
    ((bf162*)g_Alo)[i*2] = l0; ((bf162*)g_Alo)[i*2+1] = l1;
}

// ---------------- GEMM: C(128x128) = A @ W^T, 3-pass split, 64x64 warp tiles ----------------
#define BUFE 4096
#define BUFBYTES 8192u

__global__ __launch_bounds__(128) void gemm_mma(const float* __restrict__ rc,
                                                const float* __restrict__ rs,
                                                float* __restrict__ Co, int wsel, int mode) {
    __shared__ __align__(16) bf16 As[3*BUFE], Bs[3*BUFE];
    const int tid = threadIdx.x, w = tid >> 5, lane = tid & 31;
    const int wm = w & 1, wn = w >> 1;
    const int m0 = blockIdx.x * 128, n0 = blockIdx.y * 128;
    const bf16* Ahi = (mode == 3) ? g_Ahi : g_xhi;
    const bf16* Alo = (mode == 3) ? g_Alo : g_xlo;
    const bf16* Bhi = g_Whi[wsel];
    const bf16* Blo = g_Wlo[wsel];

    float acc[128];
#pragma unroll
    for (int i = 0; i < 128; i++) acc[i] = 0.f;

    const int row_l = tid >> 2, cch = tid & 3, c8 = cch * 8;
    uint32_t doff[4];
#pragma unroll
    for (int t = 0; t < 4; t++) {
        int r = t * 32 + row_l;
        doff[t] = (uint32_t)(r * 64 + ((cch ^ ((r >> 1) & 3)) << 4));
    }
    const uint32_t sA = smem_u32(As), sB = smem_u32(Bs);
    const int NS = 192;

#define G_ISSUE(st, bi) do {                                                       \
        int _p = (st) >> 6, _k0 = ((st) & 63) << 5;                                \
        const bf16* _Ap = (_p < 2) ? Ahi : Alo;                                    \
        const bf16* _Bp = (_p == 1) ? Blo : Bhi;                                   \
        uint32_t _ba = sA + (uint32_t)(bi) * BUFBYTES;                             \
        uint32_t _bb = sB + (uint32_t)(bi) * BUFBYTES;                             \
        _Pragma("unroll")                                                          \
        for (int _t = 0; _t < 4; _t++) {                                           \
            int _r = _t * 32 + row_l;                                              \
            CP16(_ba + doff[_t], _Ap + (size_t)(m0 + _r) * Dsz + _k0 + c8);        \
            CP16(_bb + doff[_t], _Bp + (size_t)(n0 + _r) * Dsz + _k0 + c8);        \
        }                                                                          \
        CP_COMMIT();                                                                \
    } while (0)

    G_ISSUE(0, 0);
    G_ISSUE(1, 1);

    int bi = 0, ii = 2;
    for (int s = 0; s < NS; s++) {
        if (s < NS - 1) CP_WAIT1(); else CP_WAIT0();
        __syncthreads();
        if (s + 2 < NS) {
            G_ISSUE(s + 2, ii);
            ii = (ii == 2) ? 0 : ii + 1;
        }
        uint32_t bufA = sA + (uint32_t)bi * BUFBYTES;
        uint32_t bufB = sB + (uint32_t)bi * BUFBYTES;
        bi = (bi == 2) ? 0 : bi + 1;
#pragma unroll
        for (int ks = 0; ks < 2; ks++) {
            int cb = ks * 2 + (lane >> 4);
            uint32_t am[4][4], bm[4][4];
#pragma unroll
            for (int mi = 0; mi < 4; mi++) {
                int r = wm * 64 + mi * 16 + (lane & 15);
                ldsm4(am[mi], bufA + (uint32_t)(r * 64 + ((cb ^ ((r >> 1) & 3)) << 4)));
            }
#pragma unroll
            for (int g = 0; g < 4; g++) {
                int r = wn * 64 + g * 16 + (lane & 15);
                ldsm4(bm[g], bufB + (uint32_t)(r * 64 + ((cb ^ ((r >> 1) & 3)) << 4)));
            }
#pragma unroll
            for (int mi = 0; mi < 4; mi++)
#pragma unroll
                for (int g = 0; g < 4; g++) {
                    mma16816(&acc[(mi * 8 + 2 * g + 0) * 4], am[mi], bm[g][0], bm[g][2]);
                    mma16816(&acc[(mi * 8 + 2 * g + 1) * 4], am[mi], bm[g][1], bm[g][3]);
                }
        }
    }

    // epilogue
    const int l4 = lane >> 2, lm = lane & 3;
    bf16* dsthi = (mode == 0) ? g_Qhi : g_Khi;
    bf16* dstlo = (mode == 0) ? g_Qlo : g_Klo;
#pragma unroll
    for (int mi = 0; mi < 4; mi++)
#pragma unroll
        for (int nb = 0; nb < 8; nb++)
#pragma unroll
            for (int rh = 0; rh < 2; rh++) {
                float v0 = acc[(mi * 8 + nb) * 4 + rh * 2 + 0];
                float v1 = acc[(mi * 8 + nb) * 4 + rh * 2 + 1];
                int row = m0 + wm * 64 + mi * 16 + l4 + rh * 8;
                int col = n0 + wn * 64 + nb * 8 + lm * 2;
                size_t idx = ((size_t)row << 11) + col;
                if (mode <= 1) {
                    int p = (col & 127) >> 1, srow = row & (Ssz - 1);
                    float cc = rc[srow * 64 + p], sn = rs[srow * 64 + p];
                    float re = v0 * cc - v1 * sn, im = v0 * sn + v1 * cc;
                    bf16 rh16 = __float2bfloat16(re), ih16 = __float2bfloat16(im);
                    bf162 hh{rh16, ih16};
                    bf162 ll{__float2bfloat16(re - __bfloat162float(rh16)),
                             __float2bfloat16(im - __bfloat162float(ih16))};
                    *(bf162*)(dsthi + idx) = hh;
                    *(bf162*)(dstlo + idx) = ll;
                } else {
                    float* dst = (mode == 2) ? g_V : Co;
                    *(float2*)(dst + idx) = make_float2(v0, v1);
                }
            }
}

// ---------------- LSE + diag weights: persistent-Q, K streaming ----------------
// dyn smem: [0,65536) Q persistent (hi@0, lo@32768; row*256 + ((ch^(r&7))<<4))
//           [65536,90112) K ring 3x8KB; [90112,90624) diag; [90624,91648) tmp
#define L_SMEM 91648

__global__ __launch_bounds__(128) void lse_mma() {
    extern __shared__ __align__(16) char smem[];
    const uint32_t sQ = smem_u32(smem);
    const uint32_t sK = sQ + 65536u;
    float* diag = (float*)(smem + 90112);
    float* tmp  = (float*)(smem + 90624);
    const int tid = threadIdx.x, w = tid >> 5, lane = tid & 31;
    const int wm = w & 1, wn = w >> 1;
    const int q0 = blockIdx.x * 128, h = blockIdx.y, b = blockIdx.z;
    const float scale = 0.08838834764831845f;
    const size_t qbase = (((size_t)(b * Ssz + q0)) << 11) + h * DHsz;
    const size_t kbb   = (((size_t)(b * Ssz)) << 11) + h * DHsz;
    const int row_l = tid >> 2, cch = tid & 3, c8 = cch * 8;
    uint32_t doff[4];
#pragma unroll
    for (int t = 0; t < 4; t++) {
        int r = t * 32 + row_l;
        doff[t] = (uint32_t)(r * 64 + ((cch ^ ((r >> 1) & 3)) << 4));
    }

    // persistent Q load (one cp.async group)
#pragma unroll
    for (int i = 0; i < 32; i++) {
        int u = tid + i * 128;
        int p = u >> 11, v = u & 2047, r = v >> 4, ch = v & 15;
        const bf16* src = (p ? g_Qlo : g_Qhi) + qbase + ((size_t)r << 11) + ch * 8;
        CP16(sQ + (uint32_t)(p * 32768 + r * 256 + ((ch ^ (r & 7)) << 4)), src);
    }
    CP_COMMIT();

    const int NS = 192;
#define L_ISSUE(st, bix) do {                                                      \
        int _c = (st) / 12, _j = (st) % 12, _p = _j >> 2, _dh0 = (_j & 3) << 5;   \
        const bf16* _Kp = (_p == 1) ? g_Klo : g_Khi;                              \
        size_t _kb = kbb + ((size_t)(_c * 128) << 11) + _dh0;                     \
        uint32_t _bk = sK + (uint32_t)(bix) * BUFBYTES;                           \
        _Pragma("unroll")                                                          \
        for (int _t = 0; _t < 4; _t++)                                            \
            CP16(_bk + doff[_t], _Kp + _kb + ((size_t)(_t * 32 + row_l) << 11) + c8); \
        CP_COMMIT();                                                                \
    } while (0)

    L_ISSUE(0, 0);
    L_ISSUE(1, 1);

    float acc[128];
#pragma unroll
    for (int i = 0; i < 128; i++) acc[i] = 0.f;
    float rsacc[8] = {0.f,0.f,0.f,0.f,0.f,0.f,0.f,0.f};
    const int l4 = lane >> 2, lm = lane & 3;

    int bi = 0, ii = 2, j = 0, cnum = 0;
    for (int s = 0; s < NS; s++) {
        if (s < NS - 1) CP_WAIT1(); else CP_WAIT0();
        __syncthreads();
        if (s + 2 < NS) {
            L_ISSUE(s + 2, ii);
            ii = (ii == 2) ? 0 : ii + 1;
        }
        uint32_t bufK = sK + (uint32_t)bi * BUFBYTES;
        bi = (bi == 2) ? 0 : bi + 1;
        int p = j >> 2;
        uint32_t qpart = (p == 2) ? 32768u : 0u;
        int qchb = (j & 3) * 4;
#pragma unroll
        for (int ks = 0; ks < 2; ks++) {
            int cb = ks * 2 + (lane >> 4);
            uint32_t am[4][4], bm[4][4];
#pragma unroll
            for (int mi = 0; mi < 4; mi++) {
                int r = wm * 64 + mi * 16 + (lane & 15);
                int ch = qchb + cb;
                ldsm4(am[mi], sQ + qpart + (uint32_t)(r * 256 + ((ch ^ (r & 7)) << 4)));
            }
#pragma unroll
            for (int g = 0; g < 4; g++) {
                int r = wn * 64 + g * 16 + (lane & 15);
                ldsm4(bm[g], bufK + (uint32_t)(r * 64 + ((cb ^ ((r >> 1) & 3)) << 4)));
            }
#pragma unroll
            for (int mi = 0; mi < 4; mi++)
#pragma unroll
                for (int g = 0; g < 4; g++) {
                    mma16816(&acc[(mi * 8 + 2 * g + 0) * 4], am[mi], bm[g][0], bm[g][2]);
                    mma16816(&acc[(mi * 8 + 2 * g + 1) * 4], am[mi], bm[g][1], bm[g][3]);
                }
        }
        if (++j == 12) {
            j = 0;
#pragma unroll
            for (int mi = 0; mi < 4; mi++)
#pragma unroll
                for (int rh = 0; rh < 2; rh++) {
                    float pp = 0.f;
#pragma unroll
                    for (int nb = 0; nb < 8; nb++) {
                        pp += __expf(acc[(mi * 8 + nb) * 4 + rh * 2 + 0] * scale);
                        pp += __expf(acc[(mi * 8 + nb) * 4 + rh * 2 + 1] * scale);
                    }
                    rsacc[mi * 2 + rh] += pp;
                }
            if (cnum == (int)blockIdx.x) {
#pragma unroll
                for (int mi = 0; mi < 4; mi++)
#pragma unroll
                    for (int nb = 0; nb < 8; nb++)
#pragma unroll
                        for (int rh = 0; rh < 2; rh++) {
                            int row = wm * 64 + mi * 16 + l4 + rh * 8;
                            int col = wn * 64 + nb * 8 + lm * 2;
                            if (row == col)     diag[row] = acc[(mi * 8 + nb) * 4 + rh * 2 + 0];
                            if (row == col + 1) diag[row] = acc[(mi * 8 + nb) * 4 + rh * 2 + 1];
                        }
            }
            cnum++;
#pragma unroll
            for (int i = 0; i < 128; i++) acc[i] = 0.f;
        }
    }

#pragma unroll
    for (int i = 0; i < 8; i++) {
        rsacc[i] += __shfl_xor_sync(0xffffffffu, rsacc[i], 1);
        rsacc[i] += __shfl_xor_sync(0xffffffffu, rsacc[i], 2);
    }
    if (lm == 0) {
#pragma unroll
        for (int mi = 0; mi < 4; mi++)
#pragma unroll
            for (int rh = 0; rh < 2; rh++)
                tmp[wn * 128 + wm * 64 + mi * 16 + rh * 8 + l4] = rsacc[mi * 2 + rh];
    }
    __syncthreads();
    if (tid < 128) {
        float sum = tmp[tid] + tmp[128 + tid];
        g_w[(((size_t)b * Hn + h) << 11) + q0 + tid] =
            __expf(diag[tid] * scale - logf(sum));
    }
}

// ---------------- launch ----------------
extern "C" void kernel_launch(void* const* d_in, const int* in_sizes, int n_in,
                              void* d_out, int out_size) {
    const float* x  = (const float*)d_in[0];
    const float* rc = (const float*)d_in[1];
    const float* rs = (const float*)d_in[2];
    const float* W[4] = { (const float*)d_in[3], (const float*)d_in[4],
                          (const float*)d_in[5], (const float*)d_in[6] };
    float* out = (float*)d_out;

    cudaFuncSetAttribute(lse_mma, cudaFuncAttributeMaxDynamicSharedMemorySize, L_SMEM);

    split_kernel<<<(Msz * Dsz / 4 + 255) / 256, 256>>>(x, 4, Msz * Dsz / 4);
    for (int i = 0; i < 4; i++)
        split_kernel<<<(Dsz * Dsz / 4 + 255) / 256, 256>>>(W[i], i, Dsz * Dsz / 4);

    dim3 gg(Msz / 128, Dsz / 128);          // (32, 16)
    gemm_mma<<<gg, 128>>>(rc, rs, nullptr, 0, 0);   // Q + rope
    gemm_mma<<<gg, 128>>>(rc, rs, nullptr, 1, 1);   // K + rope
    gemm_mma<<<gg, 128>>>(rc, rs, nullptr, 2, 2);   // V

    lse_mma<<<dim3(Ssz / 128, Hn, Bsz), 128, L_SMEM>>>();   // 512 blocks, writes g_w

    wvsplit_kernel<<<Msz * Dsz / 4 / 256, 256>>>();

    gemm_mma<<<gg, 128>>>(rc, rs, out, 3, 3);       // (w*V) @ Wo^T
}

// round 7
// speedup vs baseline: 1.0920x; 1.0920x over previous
#include <cuda_runtime.h>
#include <cuda_bf16.h>
#include <cstdint>

#define Bsz 2
#define Ssz 2048
#define Dsz 2048
#define Hn 16
#define DHsz 128
#define Msz (Bsz*Ssz)

typedef __nv_bfloat16 bf16;
typedef __nv_bfloat162 bf162;

__device__ __align__(16) bf16 g_xhi[(size_t)Msz*Dsz], g_xlo[(size_t)Msz*Dsz];
__device__ __align__(16) bf16 g_Whi[4][(size_t)Dsz*Dsz], g_Wlo[4][(size_t)Dsz*Dsz];
__device__ __align__(16) bf16 g_Qhi[(size_t)Msz*Dsz], g_Qlo[(size_t)Msz*Dsz];
__device__ __align__(16) bf16 g_Khi[(size_t)Msz*Dsz], g_Klo[(size_t)Msz*Dsz];
__device__ __align__(16) float g_V[(size_t)Msz*Dsz];
__device__ __align__(16) bf16 g_Ahi[(size_t)Msz*Dsz], g_Alo[(size_t)Msz*Dsz];
__device__ float g_w[Bsz*Hn*Ssz];

__device__ __forceinline__ uint32_t smem_u32(const void* p) {
    uint32_t a;
    asm("{ .reg .u64 t; cvta.to.shared.u64 t, %1; cvt.u32.u64 %0, t; }" : "=r"(a) : "l"(p));
    return a;
}
__device__ __forceinline__ void ldsm4(uint32_t* r, uint32_t a) {
    asm volatile("ldmatrix.sync.aligned.m8n8.x4.shared.b16 {%0,%1,%2,%3}, [%4];"
                 : "=r"(r[0]), "=r"(r[1]), "=r"(r[2]), "=r"(r[3]) : "r"(a));
}
__device__ __forceinline__ void mma16816(float* c, const uint32_t* a, uint32_t b0, uint32_t b1) {
    asm volatile("mma.sync.aligned.m16n8k16.row.col.f32.bf16.bf16.f32 "
                 "{%0,%1,%2,%3},{%4,%5,%6,%7},{%8,%9},{%0,%1,%2,%3};"
                 : "+f"(c[0]), "+f"(c[1]), "+f"(c[2]), "+f"(c[3])
                 : "r"(a[0]), "r"(a[1]), "r"(a[2]), "r"(a[3]), "r"(b0), "r"(b1));
}
#define CP16(dst, src) asm volatile("cp.async.cg.shared.global [%0], [%1], 16;" :: "r"(dst), "l"(src))
#define CP_COMMIT()    asm volatile("cp.async.commit_group;" ::: "memory")
#define CP_WAIT1()     asm volatile("cp.async.wait_group 1;" ::: "memory")
#define CP_WAIT0()     asm volatile("cp.async.wait_group 0;" ::: "memory")

// ---------------- elementwise ----------------
__global__ __launch_bounds__(256) void split_kernel(const float* __restrict__ src, int sel, int n4) {
    int i = blockIdx.x * 256 + threadIdx.x;
    if (i >= n4) return;
    bf16* hi = (sel == 4) ? g_xhi : g_Whi[sel];
    bf16* lo = (sel == 4) ? g_xlo : g_Wlo[sel];
    float4 v = ((const float4*)src)[i];
    bf16 a = __float2bfloat16(v.x), b = __float2bfloat16(v.y);
    bf16 c = __float2bfloat16(v.z), d = __float2bfloat16(v.w);
    bf162 h0{a,b}, h1{c,d};
    ((bf162*)hi)[i*2] = h0; ((bf162*)hi)[i*2+1] = h1;
    bf162 l0{__float2bfloat16(v.x - __bfloat162float(a)), __float2bfloat16(v.y - __bfloat162float(b))};
    bf162 l1{__float2bfloat16(v.z - __bfloat162float(c)), __float2bfloat16(v.w - __bfloat162float(d))};
    ((bf162*)lo)[i*2] = l0; ((bf162*)lo)[i*2+1] = l1;
}

__global__ __launch_bounds__(256) void wvsplit_kernel() {
    int i = blockIdx.x * 256 + threadIdx.x;
    int e = i * 4, m = e >> 11, d = e & 2047;
    float wv = g_w[(((m >> 11) * Hn + (d >> 7)) << 11) + (m & 2047)];
    float4 v = ((const float4*)g_V)[i];
    v.x *= wv; v.y *= wv; v.z *= wv; v.w *= wv;
    bf16 a = __float2bfloat16(v.x), b = __float2bfloat16(v.y);
    bf16 c = __float2bfloat16(v.z), dd = __float2bfloat16(v.w);
    bf162 h0{a,b}, h1{c,dd};
    ((bf162*)g_Ahi)[i*2] = h0; ((bf162*)g_Ahi)[i*2+1] = h1;
    bf162 l0{__float2bfloat16(v.x - __bfloat162float(a)), __float2bfloat16(v.y - __bfloat162float(b))};
    bf162 l1{__float2bfloat16(v.z - __bfloat162float(c)), __float2bfloat16(v.w - __bfloat162float(dd))};
    ((bf162*)g_Alo)[i*2] = l0; ((bf162*)g_Alo)[i*2+1] = l1;
}

// ---------------- GEMM (round-5 best config): 256 thr, 32x64 warp tiles, 3-stage ----------------
#define BUFE 4096
#define BUFBYTES 8192u

__global__ __launch_bounds__(256) void gemm_mma(const float* __restrict__ rc,
                                                const float* __restrict__ rs,
                                                float* __restrict__ Co, int wsel, int mode) {
    __shared__ __align__(16) bf16 As[3*BUFE], Bs[3*BUFE];
    const int tid = threadIdx.x, w = tid >> 5, lane = tid & 31;
    const int wm = w & 3, wn = w >> 2;
    const int m0 = blockIdx.x * 128, n0 = blockIdx.y * 128;
    const bf16* Ahi = (mode == 3) ? g_Ahi : g_xhi;
    const bf16* Alo = (mode == 3) ? g_Alo : g_xlo;
    const bf16* Bhi = g_Whi[wsel];
    const bf16* Blo = g_Wlo[wsel];

    float acc[64];
#pragma unroll
    for (int i = 0; i < 64; i++) acc[i] = 0.f;

    const int row_l = tid >> 2, cch = tid & 3, c8 = cch * 8;
    uint32_t doff[2];
#pragma unroll
    for (int t = 0; t < 2; t++) {
        int r = t * 64 + row_l;
        doff[t] = (uint32_t)(r * 64 + ((cch ^ ((r >> 1) & 3)) << 4));
    }
    const uint32_t sA = smem_u32(As), sB = smem_u32(Bs);
    const int NS = 192;

#define G_ISSUE(st, bi) do {                                                   \
        int _p = (st) >> 6, _k0 = ((st) & 63) << 5;                            \
        const bf16* _Ap = (_p < 2) ? Ahi : Alo;                                \
        const bf16* _Bp = (_p == 1) ? Blo : Bhi;                               \
        uint32_t _ba = sA + (uint32_t)(bi) * BUFBYTES;                         \
        uint32_t _bb = sB + (uint32_t)(bi) * BUFBYTES;                         \
        CP16(_ba + doff[0], _Ap + (size_t)(m0 + row_l) * Dsz + _k0 + c8);      \
        CP16(_ba + doff[1], _Ap + (size_t)(m0 + 64 + row_l) * Dsz + _k0 + c8); \
        CP16(_bb + doff[0], _Bp + (size_t)(n0 + row_l) * Dsz + _k0 + c8);      \
        CP16(_bb + doff[1], _Bp + (size_t)(n0 + 64 + row_l) * Dsz + _k0 + c8); \
        CP_COMMIT();                                                            \
    } while (0)

    G_ISSUE(0, 0);
    G_ISSUE(1, 1);

    int bi = 0, ii = 2;
    for (int s = 0; s < NS; s++) {
        if (s < NS - 1) CP_WAIT1(); else CP_WAIT0();
        __syncthreads();
        if (s + 2 < NS) {
            G_ISSUE(s + 2, ii);
            ii = (ii == 2) ? 0 : ii + 1;
        }
        uint32_t bufA = sA + (uint32_t)bi * BUFBYTES;
        uint32_t bufB = sB + (uint32_t)bi * BUFBYTES;
        bi = (bi == 2) ? 0 : bi + 1;
#pragma unroll
        for (int ks = 0; ks < 2; ks++) {
            int cb = ks * 2 + (lane >> 4);
            uint32_t am[2][4], bm[4][4];
            int rA0 = wm * 32 + (lane & 15);
#pragma unroll
            for (int mi = 0; mi < 2; mi++) {
                int r = rA0 + mi * 16;
                ldsm4(am[mi], bufA + (uint32_t)(r * 64 + ((cb ^ ((r >> 1) & 3)) << 4)));
            }
#pragma unroll
            for (int nb = 0; nb < 4; nb++) {
                int r = wn * 64 + nb * 16 + (lane & 15);
                ldsm4(bm[nb], bufB + (uint32_t)(r * 64 + ((cb ^ ((r >> 1) & 3)) << 4)));
            }
#pragma unroll
            for (int mi = 0; mi < 2; mi++)
#pragma unroll
                for (int nb = 0; nb < 4; nb++) {
                    mma16816(&acc[(mi * 8 + nb * 2 + 0) * 4], am[mi], bm[nb][0], bm[nb][2]);
                    mma16816(&acc[(mi * 8 + nb * 2 + 1) * 4], am[mi], bm[nb][1], bm[nb][3]);
                }
        }
    }

    // epilogue
    const int l4 = lane >> 2, lm = lane & 3;
    bf16* dsthi = (mode == 0) ? g_Qhi : g_Khi;
    bf16* dstlo = (mode == 0) ? g_Qlo : g_Klo;
#pragma unroll
    for (int mi = 0; mi < 2; mi++)
#pragma unroll
        for (int nb = 0; nb < 4; nb++)
#pragma unroll
            for (int j = 0; j < 2; j++)
#pragma unroll
                for (int rh = 0; rh < 2; rh++) {
                    float v0 = acc[(mi * 8 + nb * 2 + j) * 4 + rh * 2 + 0];
                    float v1 = acc[(mi * 8 + nb * 2 + j) * 4 + rh * 2 + 1];
                    int row = m0 + wm * 32 + mi * 16 + l4 + rh * 8;
                    int col = n0 + wn * 64 + nb * 16 + j * 8 + lm * 2;
                    size_t idx = ((size_t)row << 11) + col;
                    if (mode <= 1) {
                        int p = (col & 127) >> 1, srow = row & (Ssz - 1);
                        float cc = rc[srow * 64 + p], sn = rs[srow * 64 + p];
                        float re = v0 * cc - v1 * sn, im = v0 * sn + v1 * cc;
                        bf16 rh16 = __float2bfloat16(re), ih16 = __float2bfloat16(im);
                        bf162 hh{rh16, ih16};
                        bf162 ll{__float2bfloat16(re - __bfloat162float(rh16)),
                                 __float2bfloat16(im - __bfloat162float(ih16))};
                        *(bf162*)(dsthi + idx) = hh;
                        *(bf162*)(dstlo + idx) = ll;
                    } else {
                        float* dst = (mode == 2) ? g_V : Co;
                        *(float2*)(dst + idx) = make_float2(v0, v1);
                    }
                }
}

// ---------------- LSE + diag weights: persistent-Q, K streaming, 256 thr ----------------
// dyn smem: [0,65536) Q persistent (hi@0, lo@32768; addr = r*256 + ((ch^(r&7))<<4))
//           [65536,90112) K ring 3x8KB; [90112,90624) diag; [90624,91648) tmp
#define L_SMEM 91648

__global__ __launch_bounds__(256) void lse_mma() {
    extern __shared__ __align__(16) char smem[];
    const uint32_t sQ = smem_u32(smem);
    const uint32_t sK = sQ + 65536u;
    float* diag = (float*)(smem + 90112);
    float* tmp  = (float*)(smem + 90624);
    const int tid = threadIdx.x, w = tid >> 5, lane = tid & 31;
    const int wm = w & 3, wn = w >> 2;
    const int q0 = blockIdx.x * 128, h = blockIdx.y, b = blockIdx.z;
    const float scale = 0.08838834764831845f;
    const size_t qbase = (((size_t)(b * Ssz + q0)) << 11) + h * DHsz;
    const size_t kbb   = (((size_t)(b * Ssz)) << 11) + h * DHsz;
    const int row_l = tid >> 2, cch = tid & 3, c8 = cch * 8;
    uint32_t doff[2];
#pragma unroll
    for (int t = 0; t < 2; t++) {
        int r = t * 64 + row_l;
        doff[t] = (uint32_t)(r * 64 + ((cch ^ ((r >> 1) & 3)) << 4));
    }

    // persistent Q (hi+lo) in one commit group: 4096 16B chunks / 256 threads
#pragma unroll
    for (int i = 0; i < 16; i++) {
        int u = tid + i * 256;
        int p = u >> 11, v = u & 2047, r = v >> 4, ch = v & 15;
        const bf16* src = (p ? g_Qlo : g_Qhi) + qbase + ((size_t)r << 11) + ch * 8;
        CP16(sQ + (uint32_t)(p * 32768 + r * 256 + ((ch ^ (r & 7)) << 4)), src);
    }
    CP_COMMIT();

    const int NS = 192;   // 16 chunks x 12 slabs (3 passes x 4 dh-slabs)
#define L_ISSUE(st, bix) do {                                                     \
        int _c = (st) / 12, _j = (st) % 12, _p = _j >> 2, _dh0 = (_j & 3) << 5;   \
        const bf16* _Kp = (_p == 1) ? g_Klo : g_Khi;                              \
        size_t _kb = kbb + ((size_t)(_c * 128) << 11) + _dh0;                     \
        uint32_t _bk = sK + (uint32_t)(bix) * BUFBYTES;                           \
        CP16(_bk + doff[0], _Kp + _kb + ((size_t)row_l << 11) + c8);              \
        CP16(_bk + doff[1], _Kp + _kb + ((size_t)(64 + row_l) << 11) + c8);       \
        CP_COMMIT();                                                               \
    } while (0)

    L_ISSUE(0, 0);
    L_ISSUE(1, 1);

    float acc[64];
#pragma unroll
    for (int i = 0; i < 64; i++) acc[i] = 0.f;
    float rsacc[4] = {0.f, 0.f, 0.f, 0.f};
    const int l4 = lane >> 2, lm = lane & 3;

    int bi = 0, ii = 2, j = 0, cnum = 0;
    for (int s = 0; s < NS; s++) {
        if (s < NS - 1) CP_WAIT1(); else CP_WAIT0();
        __syncthreads();
        if (s + 2 < NS) {
            L_ISSUE(s + 2, ii);
            ii = (ii == 2) ? 0 : ii + 1;
        }
        uint32_t bufK = sK + (uint32_t)bi * BUFBYTES;
        bi = (bi == 2) ? 0 : bi + 1;
        uint32_t qpart = ((j >> 2) == 2) ? 32768u : 0u;
        int qchb = (j & 3) * 4;
#pragma unroll
        for (int ks = 0; ks < 2; ks++) {
            int cb = ks * 2 + (lane >> 4);
            uint32_t am[2][4], bm[4][4];
            int rA0 = wm * 32 + (lane & 15);
#pragma unroll
            for (int mi = 0; mi < 2; mi++) {
                int r = rA0 + mi * 16;
                int ch = qchb + cb;
                ldsm4(am[mi], sQ + qpart + (uint32_t)(r * 256 + ((ch ^ (r & 7)) << 4)));
            }
#pragma unroll
            for (int nb = 0; nb < 4; nb++) {
                int r = wn * 64 + nb * 16 + (lane & 15);
                ldsm4(bm[nb], bufK + (uint32_t)(r * 64 + ((cb ^ ((r >> 1) & 3)) << 4)));
            }
#pragma unroll
            for (int mi = 0; mi < 2; mi++)
#pragma unroll
                for (int nb = 0; nb < 4; nb++) {
                    mma16816(&acc[(mi * 8 + nb * 2 + 0) * 4], am[mi], bm[nb][0], bm[nb][2]);
                    mma16816(&acc[(mi * 8 + nb * 2 + 1) * 4], am[mi], bm[nb][1], bm[nb][3]);
                }
        }
        if (++j == 12) {   // key chunk complete
            j = 0;
#pragma unroll
            for (int mi = 0; mi < 2; mi++)
#pragma unroll
                for (int rh = 0; rh < 2; rh++) {
                    float pp = 0.f;
#pragma unroll
                    for (int nb = 0; nb < 4; nb++)
#pragma unroll
                        for (int jj = 0; jj < 2; jj++) {
                            pp += __expf(acc[(mi * 8 + nb * 2 + jj) * 4 + rh * 2 + 0] * scale);
                            pp += __expf(acc[(mi * 8 + nb * 2 + jj) * 4 + rh * 2 + 1] * scale);
                        }
                    rsacc[mi * 2 + rh] += pp;
                }
            if (cnum == (int)blockIdx.x) {   // diagonal chunk: stash q_s.k_s
#pragma unroll
                for (int mi = 0; mi < 2; mi++)
#pragma unroll
                    for (int nb = 0; nb < 4; nb++)
#pragma unroll
                        for (int jj = 0; jj < 2; jj++)
#pragma unroll
                            for (int rh = 0; rh < 2; rh++) {
                                int row = wm * 32 + mi * 16 + l4 + rh * 8;
                                int col = wn * 64 + nb * 16 + jj * 8 + lm * 2;
                                if (row == col)
                                    diag[row] = acc[(mi * 8 + nb * 2 + jj) * 4 + rh * 2 + 0];
                                if (row == col + 1)
                                    diag[row] = acc[(mi * 8 + nb * 2 + jj) * 4 + rh * 2 + 1];
                            }
            }
            cnum++;
#pragma unroll
            for (int i = 0; i < 64; i++) acc[i] = 0.f;
        }
    }

    // reduce over 4 lanes sharing a row, combine 2 N-warps, write w
#pragma unroll
    for (int i = 0; i < 4; i++) {
        rsacc[i] += __shfl_xor_sync(0xffffffffu, rsacc[i], 1);
        rsacc[i] += __shfl_xor_sync(0xffffffffu, rsacc[i], 2);
    }
    if (lm == 0) {
#pragma unroll
        for (int mi = 0; mi < 2; mi++)
#pragma unroll
            for (int rh = 0; rh < 2; rh++)
                tmp[wn * 128 + wm * 32 + mi * 16 + rh * 8 + l4] = rsacc[mi * 2 + rh];
    }
    __syncthreads();
    if (tid < 128) {
        float sum = tmp[tid] + tmp[128 + tid];
        g_w[(((size_t)b * Hn + h) << 11) + q0 + tid] =
            __expf(diag[tid] * scale - logf(sum));
    }
}

// ---------------- launch ----------------
extern "C" void kernel_launch(void* const* d_in, const int* in_sizes, int n_in,
                              void* d_out, int out_size) {
    const float* x  = (const float*)d_in[0];
    const float* rc = (const float*)d_in[1];
    const float* rs = (const float*)d_in[2];
    const float* W[4] = { (const float*)d_in[3], (const float*)d_in[4],
                          (const float*)d_in[5], (const float*)d_in[6] };
    float* out = (float*)d_out;

    cudaFuncSetAttribute(lse_mma, cudaFuncAttributeMaxDynamicSharedMemorySize, L_SMEM);

    split_kernel<<<(Msz * Dsz / 4 + 255) / 256, 256>>>(x, 4, Msz * Dsz / 4);
    for (int i = 0; i < 4; i++)
        split_kernel<<<(Dsz * Dsz / 4 + 255) / 256, 256>>>(W[i], i, Dsz * Dsz / 4);

    dim3 gg(Msz / 128, Dsz / 128);          // (32, 16)
    gemm_mma<<<gg, 256>>>(rc, rs, nullptr, 0, 0);   // Q + rope
    gemm_mma<<<gg, 256>>>(rc, rs, nullptr, 1, 1);   // K + rope
    gemm_mma<<<gg, 256>>>(rc, rs, nullptr, 2, 2);   // V

    lse_mma<<<dim3(Ssz / 128, Hn, Bsz), 256, L_SMEM>>>();   // writes g_w directly

    wvsplit_kernel<<<Msz * Dsz / 4 / 256, 256>>>();

    gemm_mma<<<gg, 256>>>(rc, rs, out, 3, 3);       // (w*V) @ Wo^T
}

// round 8
// speedup vs baseline: 1.0978x; 1.0053x over previous
#include <cuda_runtime.h>
#include <cuda_bf16.h>
#include <cstdint>

#define Bsz 2
#define Ssz 2048
#define Dsz 2048
#define Hn 16
#define DHsz 128
#define Msz (Bsz*Ssz)

typedef __nv_bfloat16 bf16;
typedef __nv_bfloat162 bf162;

__device__ __align__(16) bf16 g_xhi[(size_t)Msz*Dsz], g_xlo[(size_t)Msz*Dsz];
__device__ __align__(16) bf16 g_Whi[4][(size_t)Dsz*Dsz], g_Wlo[4][(size_t)Dsz*Dsz];
__device__ __align__(16) bf16 g_Qhi[(size_t)Msz*Dsz], g_Qlo[(size_t)Msz*Dsz];
__device__ __align__(16) bf16 g_Khi[(size_t)Msz*Dsz], g_Klo[(size_t)Msz*Dsz];
__device__ __align__(16) float g_V[(size_t)Msz*Dsz];
__device__ __align__(16) bf16 g_Ahi[(size_t)Msz*Dsz], g_Alo[(size_t)Msz*Dsz];

__device__ __forceinline__ uint32_t smem_u32(const void* p) {
    uint32_t a;
    asm("{ .reg .u64 t; cvta.to.shared.u64 t, %1; cvt.u32.u64 %0, t; }" : "=r"(a) : "l"(p));
    return a;
}
__device__ __forceinline__ void ldsm4(uint32_t* r, uint32_t a) {
    asm volatile("ldmatrix.sync.aligned.m8n8.x4.shared.b16 {%0,%1,%2,%3}, [%4];"
                 : "=r"(r[0]), "=r"(r[1]), "=r"(r[2]), "=r"(r[3]) : "r"(a));
}
__device__ __forceinline__ void mma16816(float* c, const uint32_t* a, uint32_t b0, uint32_t b1) {
    asm volatile("mma.sync.aligned.m16n8k16.row.col.f32.bf16.bf16.f32 "
                 "{%0,%1,%2,%3},{%4,%5,%6,%7},{%8,%9},{%0,%1,%2,%3};"
                 : "+f"(c[0]), "+f"(c[1]), "+f"(c[2]), "+f"(c[3])
                 : "r"(a[0]), "r"(a[1]), "r"(a[2]), "r"(a[3]), "r"(b0), "r"(b1));
}
#define CP16(dst, src) asm volatile("cp.async.cg.shared.global [%0], [%1], 16;" :: "r"(dst), "l"(src))
#define CP_COMMIT()    asm volatile("cp.async.commit_group;" ::: "memory")
#define CP_WAIT2()     asm volatile("cp.async.wait_group 2;" ::: "memory")
#define CP_WAIT1()     asm volatile("cp.async.wait_group 1;" ::: "memory")
#define CP_WAIT0()     asm volatile("cp.async.wait_group 0;" ::: "memory")

// ---------------- elementwise ----------------
__global__ __launch_bounds__(256) void split_kernel(const float* __restrict__ src, int sel, int n4) {
    int i = blockIdx.x * 256 + threadIdx.x;
    if (i >= n4) return;
    bf16* hi = (sel == 4) ? g_xhi : g_Whi[sel];
    bf16* lo = (sel == 4) ? g_xlo : g_Wlo[sel];
    float4 v = ((const float4*)src)[i];
    bf16 a = __float2bfloat16(v.x), b = __float2bfloat16(v.y);
    bf16 c = __float2bfloat16(v.z), d = __float2bfloat16(v.w);
    bf162 h0{a,b}, h1{c,d};
    ((bf162*)hi)[i*2] = h0; ((bf162*)hi)[i*2+1] = h1;
    bf162 l0{__float2bfloat16(v.x - __bfloat162float(a)), __float2bfloat16(v.y - __bfloat162float(b))};
    bf162 l1{__float2bfloat16(v.z - __bfloat162float(c)), __float2bfloat16(v.w - __bfloat162float(d))};
    ((bf162*)lo)[i*2] = l0; ((bf162*)lo)[i*2+1] = l1;
}

// ---------------- GEMM: 256 thr, 32x64 warp tiles, 4-stage cp.async ----------------
#define BUFE 4096
#define BUFBYTES 8192u
#define G_SMEM 65536

__global__ __launch_bounds__(256) void gemm_mma(const float* __restrict__ rc,
                                                const float* __restrict__ rs,
                                                float* __restrict__ Co, int wsel, int mode) {
    extern __shared__ __align__(16) char smem[];
    const int tid = threadIdx.x, w = tid >> 5, lane = tid & 31;
    const int wm = w & 3, wn = w >> 2;
    const int m0 = blockIdx.x * 128, n0 = blockIdx.y * 128;
    const bf16* Ahi = (mode == 3) ? g_Ahi : g_xhi;
    const bf16* Alo = (mode == 3) ? g_Alo : g_xlo;
    const bf16* Bhi = g_Whi[wsel];
    const bf16* Blo = g_Wlo[wsel];

    float acc[64];
#pragma unroll
    for (int i = 0; i < 64; i++) acc[i] = 0.f;

    const int row_l = tid >> 2, cch = tid & 3, c8 = cch * 8;
    uint32_t doff[2];
#pragma unroll
    for (int t = 0; t < 2; t++) {
        int r = t * 64 + row_l;
        doff[t] = (uint32_t)(r * 64 + ((cch ^ ((r >> 1) & 3)) << 4));
    }
    const uint32_t sA = smem_u32(smem), sB = sA + 32768u;
    const int NS = 192;

#define G_ISSUE(st, bi) do {                                                   \
        int _p = (st) >> 6, _k0 = ((st) & 63) << 5;                            \
        const bf16* _Ap = (_p < 2) ? Ahi : Alo;                                \
        const bf16* _Bp = (_p == 1) ? Blo : Bhi;                               \
        uint32_t _ba = sA + (uint32_t)(bi) * BUFBYTES;                         \
        uint32_t _bb = sB + (uint32_t)(bi) * BUFBYTES;                         \
        CP16(_ba + doff[0], _Ap + (size_t)(m0 + row_l) * Dsz + _k0 + c8);      \
        CP16(_ba + doff[1], _Ap + (size_t)(m0 + 64 + row_l) * Dsz + _k0 + c8); \
        CP16(_bb + doff[0], _Bp + (size_t)(n0 + row_l) * Dsz + _k0 + c8);      \
        CP16(_bb + doff[1], _Bp + (size_t)(n0 + 64 + row_l) * Dsz + _k0 + c8); \
        CP_COMMIT();                                                            \
    } while (0)

    G_ISSUE(0, 0);
    G_ISSUE(1, 1);
    G_ISSUE(2, 2);

    int bi = 0, ii = 3;
    for (int s = 0; s < NS; s++) {
        if (s + 2 < NS) CP_WAIT2(); else if (s + 1 < NS) CP_WAIT1(); else CP_WAIT0();
        __syncthreads();
        if (s + 3 < NS) {
            G_ISSUE(s + 3, ii);
            ii = (ii + 1) & 3;
        }
        uint32_t bufA = sA + (uint32_t)bi * BUFBYTES;
        uint32_t bufB = sB + (uint32_t)bi * BUFBYTES;
        bi = (bi + 1) & 3;
#pragma unroll
        for (int ks = 0; ks < 2; ks++) {
            int cb = ks * 2 + (lane >> 4);
            uint32_t am[2][4], bm[4][4];
            int rA0 = wm * 32 + (lane & 15);
#pragma unroll
            for (int mi = 0; mi < 2; mi++) {
                int r = rA0 + mi * 16;
                ldsm4(am[mi], bufA + (uint32_t)(r * 64 + ((cb ^ ((r >> 1) & 3)) << 4)));
            }
#pragma unroll
            for (int nb = 0; nb < 4; nb++) {
                int r = wn * 64 + nb * 16 + (lane & 15);
                ldsm4(bm[nb], bufB + (uint32_t)(r * 64 + ((cb ^ ((r >> 1) & 3)) << 4)));
            }
#pragma unroll
            for (int mi = 0; mi < 2; mi++)
#pragma unroll
                for (int nb = 0; nb < 4; nb++) {
                    mma16816(&acc[(mi * 8 + nb * 2 + 0) * 4], am[mi], bm[nb][0], bm[nb][2]);
                    mma16816(&acc[(mi * 8 + nb * 2 + 1) * 4], am[mi], bm[nb][1], bm[nb][3]);
                }
        }
    }

    // epilogue
    const int l4 = lane >> 2, lm = lane & 3;
    bf16* dsthi = (mode == 0) ? g_Qhi : g_Khi;
    bf16* dstlo = (mode == 0) ? g_Qlo : g_Klo;
#pragma unroll
    for (int mi = 0; mi < 2; mi++)
#pragma unroll
        for (int nb = 0; nb < 4; nb++)
#pragma unroll
            for (int j = 0; j < 2; j++)
#pragma unroll
                for (int rh = 0; rh < 2; rh++) {
                    float v0 = acc[(mi * 8 + nb * 2 + j) * 4 + rh * 2 + 0];
                    float v1 = acc[(mi * 8 + nb * 2 + j) * 4 + rh * 2 + 1];
                    int row = m0 + wm * 32 + mi * 16 + l4 + rh * 8;
                    int col = n0 + wn * 64 + nb * 16 + j * 8 + lm * 2;
                    size_t idx = ((size_t)row << 11) + col;
                    if (mode <= 1) {
                        int p = (col & 127) >> 1, srow = row & (Ssz - 1);
                        float cc = rc[srow * 64 + p], sn = rs[srow * 64 + p];
                        float re = v0 * cc - v1 * sn, im = v0 * sn + v1 * cc;
                        bf16 rh16 = __float2bfloat16(re), ih16 = __float2bfloat16(im);
                        bf162 hh{rh16, ih16};
                        bf162 ll{__float2bfloat16(re - __bfloat162float(rh16)),
                                 __float2bfloat16(im - __bfloat162float(ih16))};
                        *(bf162*)(dsthi + idx) = hh;
                        *(bf162*)(dstlo + idx) = ll;
                    } else {
                        float* dst = (mode == 2) ? g_V : Co;
                        *(float2*)(dst + idx) = make_float2(v0, v1);
                    }
                }
}

// ---------------- LSE + w + V-scale/split fused; persistent-Q, 4-stage K ring ----------------
// smem: [0,65536) Q persistent; [65536,98304) K ring 4x8KB;
//       [98304,98816) diag; [98816,99840) tmp; [99840,100352) wrow
#define L_SMEM 100352

__global__ __launch_bounds__(256) void lse_mma() {
    extern __shared__ __align__(16) char smem[];
    const uint32_t sQ = smem_u32(smem);
    const uint32_t sK = sQ + 65536u;
    float* diag = (float*)(smem + 98304);
    float* tmp  = (float*)(smem + 98816);
    float* wrow = (float*)(smem + 99840);
    const int tid = threadIdx.x, w = tid >> 5, lane = tid & 31;
    const int wm = w & 3, wn = w >> 2;
    const int q0 = blockIdx.x * 128, h = blockIdx.y, b = blockIdx.z;
    const float scale = 0.08838834764831845f;
    const size_t qbase = (((size_t)(b * Ssz + q0)) << 11) + h * DHsz;
    const size_t kbb   = (((size_t)(b * Ssz)) << 11) + h * DHsz;
    const int row_l = tid >> 2, cch = tid & 3, c8 = cch * 8;
    uint32_t doff[2];
#pragma unroll
    for (int t = 0; t < 2; t++) {
        int r = t * 64 + row_l;
        doff[t] = (uint32_t)(r * 64 + ((cch ^ ((r >> 1) & 3)) << 4));
    }

    // persistent Q (hi+lo) in one commit group
#pragma unroll
    for (int i = 0; i < 16; i++) {
        int u = tid + i * 256;
        int p = u >> 11, v = u & 2047, r = v >> 4, ch = v & 15;
        const bf16* src = (p ? g_Qlo : g_Qhi) + qbase + ((size_t)r << 11) + ch * 8;
        CP16(sQ + (uint32_t)(p * 32768 + r * 256 + ((ch ^ (r & 7)) << 4)), src);
    }
    CP_COMMIT();

    const int NS = 192;
#define L_ISSUE(st, bix) do {                                                     \
        int _c = (st) / 12, _j = (st) % 12, _p = _j >> 2, _dh0 = (_j & 3) << 5;   \
        const bf16* _Kp = (_p == 1) ? g_Klo : g_Khi;                              \
        size_t _kb = kbb + ((size_t)(_c * 128) << 11) + _dh0;                     \
        uint32_t _bk = sK + (uint32_t)(bix) * BUFBYTES;                           \
        CP16(_bk + doff[0], _Kp + _kb + ((size_t)row_l << 11) + c8);              \
        CP16(_bk + doff[1], _Kp + _kb + ((size_t)(64 + row_l) << 11) + c8);       \
        CP_COMMIT();                                                               \
    } while (0)

    L_ISSUE(0, 0);
    L_ISSUE(1, 1);
    L_ISSUE(2, 2);

    float acc[64];
#pragma unroll
    for (int i = 0; i < 64; i++) acc[i] = 0.f;
    float rsacc[4] = {0.f, 0.f, 0.f, 0.f};
    const int l4 = lane >> 2, lm = lane & 3;

    int bi = 0, ii = 3, j = 0, cnum = 0;
    for (int s = 0; s < NS; s++) {
        if (s + 2 < NS) CP_WAIT2(); else if (s + 1 < NS) CP_WAIT1(); else CP_WAIT0();
        __syncthreads();
        if (s + 3 < NS) {
            L_ISSUE(s + 3, ii);
            ii = (ii + 1) & 3;
        }
        uint32_t bufK = sK + (uint32_t)bi * BUFBYTES;
        bi = (bi + 1) & 3;
        uint32_t qpart = ((j >> 2) == 2) ? 32768u : 0u;
        int qchb = (j & 3) * 4;
#pragma unroll
        for (int ks = 0; ks < 2; ks++) {
            int cb = ks * 2 + (lane >> 4);
            uint32_t am[2][4], bm[4][4];
            int rA0 = wm * 32 + (lane & 15);
#pragma unroll
            for (int mi = 0; mi < 2; mi++) {
                int r = rA0 + mi * 16;
                int ch = qchb + cb;
                ldsm4(am[mi], sQ + qpart + (uint32_t)(r * 256 + ((ch ^ (r & 7)) << 4)));
            }
#pragma unroll
            for (int nb = 0; nb < 4; nb++) {
                int r = wn * 64 + nb * 16 + (lane & 15);
                ldsm4(bm[nb], bufK + (uint32_t)(r * 64 + ((cb ^ ((r >> 1) & 3)) << 4)));
            }
#pragma unroll
            for (int mi = 0; mi < 2; mi++)
#pragma unroll
                for (int nb = 0; nb < 4; nb++) {
                    mma16816(&acc[(mi * 8 + nb * 2 + 0) * 4], am[mi], bm[nb][0], bm[nb][2]);
                    mma16816(&acc[(mi * 8 + nb * 2 + 1) * 4], am[mi], bm[nb][1], bm[nb][3]);
                }
        }
        if (++j == 12) {   // key chunk complete
            j = 0;
#pragma unroll
            for (int mi = 0; mi < 2; mi++)
#pragma unroll
                for (int rh = 0; rh < 2; rh++) {
                    float pp = 0.f;
#pragma unroll
                    for (int nb = 0; nb < 4; nb++)
#pragma unroll
                        for (int jj = 0; jj < 2; jj++) {
                            pp += __expf(acc[(mi * 8 + nb * 2 + jj) * 4 + rh * 2 + 0] * scale);
                            pp += __expf(acc[(mi * 8 + nb * 2 + jj) * 4 + rh * 2 + 1] * scale);
                        }
                    rsacc[mi * 2 + rh] += pp;
                }
            if (cnum == (int)blockIdx.x) {   // diagonal chunk
#pragma unroll
                for (int mi = 0; mi < 2; mi++)
#pragma unroll
                    for (int nb = 0; nb < 4; nb++)
#pragma unroll
                        for (int jj = 0; jj < 2; jj++)
#pragma unroll
                            for (int rh = 0; rh < 2; rh++) {
                                int row = wm * 32 + mi * 16 + l4 + rh * 8;
                                int col = wn * 64 + nb * 16 + jj * 8 + lm * 2;
                                if (row == col)
                                    diag[row] = acc[(mi * 8 + nb * 2 + jj) * 4 + rh * 2 + 0];
                                if (row == col + 1)
                                    diag[row] = acc[(mi * 8 + nb * 2 + jj) * 4 + rh * 2 + 1];
                            }
            }
            cnum++;
#pragma unroll
            for (int i = 0; i < 64; i++) acc[i] = 0.f;
        }
    }

    // rowsum reduce -> w in smem
#pragma unroll
    for (int i = 0; i < 4; i++) {
        rsacc[i] += __shfl_xor_sync(0xffffffffu, rsacc[i], 1);
        rsacc[i] += __shfl_xor_sync(0xffffffffu, rsacc[i], 2);
    }
    if (lm == 0) {
#pragma unroll
        for (int mi = 0; mi < 2; mi++)
#pragma unroll
            for (int rh = 0; rh < 2; rh++)
                tmp[wn * 128 + wm * 32 + mi * 16 + rh * 8 + l4] = rsacc[mi * 2 + rh];
    }
    __syncthreads();
    if (tid < 128) {
        float sum = tmp[tid] + tmp[128 + tid];
        wrow[tid] = __expf(diag[tid] * scale - logf(sum));
    }
    __syncthreads();

    // fused V scale + split: A[q0..q0+127, h*128..h*128+127] = w * V
#pragma unroll
    for (int i = 0; i < 16; i++) {
        int u = tid + i * 256;          // 0..4095
        int r = u >> 5, c4 = u & 31;
        size_t idx = (((size_t)(b * Ssz + q0 + r)) << 11) + h * DHsz + c4 * 4;
        float4 v = *(const float4*)(g_V + idx);
        float wv = wrow[r];
        v.x *= wv; v.y *= wv; v.z *= wv; v.w *= wv;
        bf16 a = __float2bfloat16(v.x), bb = __float2bfloat16(v.y);
        bf16 c = __float2bfloat16(v.z), dd = __float2bfloat16(v.w);
        bf162 h0{a, bb}, h1{c, dd};
        *(bf162*)(g_Ahi + idx)     = h0;
        *(bf162*)(g_Ahi + idx + 2) = h1;
        bf162 l0{__float2bfloat16(v.x - __bfloat162float(a)),
                 __float2bfloat16(v.y - __bfloat162float(bb))};
        bf162 l1{__float2bfloat16(v.z - __bfloat162float(c)),
                 __float2bfloat16(v.w - __bfloat162float(dd))};
        *(bf162*)(g_Alo + idx)     = l0;
        *(bf162*)(g_Alo + idx + 2) = l1;
    }
}

// ---------------- launch ----------------
extern "C" void kernel_launch(void* const* d_in, const int* in_sizes, int n_in,
                              void* d_out, int out_size) {
    const float* x  = (const float*)d_in[0];
    const float* rc = (const float*)d_in[1];
    const float* rs = (const float*)d_in[2];
    const float* W[4] = { (const float*)d_in[3], (const float*)d_in[4],
                          (const float*)d_in[5], (const float*)d_in[6] };
    float* out = (float*)d_out;

    cudaFuncSetAttribute(gemm_mma, cudaFuncAttributeMaxDynamicSharedMemorySize, G_SMEM);
    cudaFuncSetAttribute(lse_mma, cudaFuncAttributeMaxDynamicSharedMemorySize, L_SMEM);

    dim3 gg(Msz / 128, Dsz / 128);          // (32, 16)
    const int wgrid = Dsz * Dsz / 4 / 256;  // 4096

    // interleaved so ncu's skip-5 lands on gemm_mma (launch 5 = gemmK)
    split_kernel<<<(Msz * Dsz / 4 + 255) / 256, 256>>>(x, 4, Msz * Dsz / 4);  // 1
    split_kernel<<<wgrid, 256>>>(W[0], 0, Dsz * Dsz / 4);                     // 2
    gemm_mma<<<gg, 256, G_SMEM>>>(rc, rs, nullptr, 0, 0);                     // 3: Q + rope
    split_kernel<<<wgrid, 256>>>(W[1], 1, Dsz * Dsz / 4);                     // 4
    gemm_mma<<<gg, 256, G_SMEM>>>(rc, rs, nullptr, 1, 1);                     // 5: K + rope
    split_kernel<<<wgrid, 256>>>(W[2], 2, Dsz * Dsz / 4);                     // 6
    gemm_mma<<<gg, 256, G_SMEM>>>(rc, rs, nullptr, 2, 2);                     // 7: V
    lse_mma<<<dim3(Ssz / 128, Hn, Bsz), 256, L_SMEM>>>();                     // 8: lse+w+A
    split_kernel<<<wgrid, 256>>>(W[3], 3, Dsz * Dsz / 4);                     // 9
    gemm_mma<<<gg, 256, G_SMEM>>>(rc, rs, out, 3, 3);                         // 10: (wV)@Wo^T
}

// round 9
// speedup vs baseline: 3.0624x; 2.7896x over previous
#include <cuda_runtime.h>
#include <cuda_fp16.h>
#include <cstdint>

#define Bsz 2
#define Ssz 2048
#define Dsz 2048
#define Hn 16
#define DHsz 128
#define Msz (Bsz*Ssz)

__device__ __align__(16) __half g_xh[(size_t)Msz*Dsz];
__device__ __align__(16) __half g_Wh[4][(size_t)Dsz*Dsz];
__device__ __align__(16) __half g_Qh[(size_t)Msz*Dsz];
__device__ __align__(16) __half g_Kh[(size_t)Msz*Dsz];
__device__ __align__(16) __half g_Vh[(size_t)Msz*Dsz];
__device__ __align__(16) __half g_Ah[(size_t)Msz*Dsz];   // 1024 * w * V

#define ASCALE 1024.0f
#define AINV   0.0009765625f

__device__ __forceinline__ uint32_t smem_u32(const void* p) {
    uint32_t a;
    asm("{ .reg .u64 t; cvta.to.shared.u64 t, %1; cvt.u32.u64 %0, t; }" : "=r"(a) : "l"(p));
    return a;
}
__device__ __forceinline__ void ldsm4(uint32_t* r, uint32_t a) {
    asm volatile("ldmatrix.sync.aligned.m8n8.x4.shared.b16 {%0,%1,%2,%3}, [%4];"
                 : "=r"(r[0]), "=r"(r[1]), "=r"(r[2]), "=r"(r[3]) : "r"(a));
}
__device__ __forceinline__ void mma16816(float* c, const uint32_t* a, uint32_t b0, uint32_t b1) {
    asm volatile("mma.sync.aligned.m16n8k16.row.col.f32.f16.f16.f32 "
                 "{%0,%1,%2,%3},{%4,%5,%6,%7},{%8,%9},{%0,%1,%2,%3};"
                 : "+f"(c[0]), "+f"(c[1]), "+f"(c[2]), "+f"(c[3])
                 : "r"(a[0]), "r"(a[1]), "r"(a[2]), "r"(a[3]), "r"(b0), "r"(b1));
}
#define CP16(dst, src) asm volatile("cp.async.cg.shared.global [%0], [%1], 16;" :: "r"(dst), "l"(src))
#define CP_COMMIT()    asm volatile("cp.async.commit_group;" ::: "memory")
#define CP_WAIT2()     asm volatile("cp.async.wait_group 2;" ::: "memory")
#define CP_WAIT1()     asm volatile("cp.async.wait_group 1;" ::: "memory")
#define CP_WAIT0()     asm volatile("cp.async.wait_group 0;" ::: "memory")

// ---------------- fp32 -> fp16 convert ----------------
__global__ __launch_bounds__(256) void half_kernel(const float* __restrict__ src, int sel, int n4) {
    int i = blockIdx.x * 256 + threadIdx.x;
    if (i >= n4) return;
    __half* dst = (sel == 4) ? g_xh : g_Wh[sel];
    float4 v = ((const float4*)src)[i];
    ((__half2*)dst)[i*2]   = __floats2half2_rn(v.x, v.y);
    ((__half2*)dst)[i*2+1] = __floats2half2_rn(v.z, v.w);
}

// ---------------- GEMM: C(128x128) = A @ W^T, 1-pass fp16, 4-stage cp.async ----------------
#define BUFBYTES 8192u
#define G_SMEM 65536

__global__ __launch_bounds__(256) void gemm_mma(const float* __restrict__ rc,
                                                const float* __restrict__ rs,
                                                float* __restrict__ Co, int wsel, int mode) {
    extern __shared__ __align__(16) char smem[];
    const int tid = threadIdx.x, w = tid >> 5, lane = tid & 31;
    const int wm = w & 3, wn = w >> 2;
    const int m0 = blockIdx.x * 128, n0 = blockIdx.y * 128;
    const __half* Ah = (mode == 3) ? g_Ah : g_xh;
    const __half* Bh = g_Wh[wsel];

    float acc[64];
#pragma unroll
    for (int i = 0; i < 64; i++) acc[i] = 0.f;

    const int row_l = tid >> 2, cch = tid & 3, c8 = cch * 8;
    uint32_t doff[2];
#pragma unroll
    for (int t = 0; t < 2; t++) {
        int r = t * 64 + row_l;
        doff[t] = (uint32_t)(r * 64 + ((cch ^ ((r >> 1) & 3)) << 4));
    }
    const uint32_t sA = smem_u32(smem), sB = sA + 32768u;
    const int NS = 64;

#define G_ISSUE(st, bi) do {                                                   \
        int _k0 = (st) << 5;                                                   \
        uint32_t _ba = sA + (uint32_t)(bi) * BUFBYTES;                         \
        uint32_t _bb = sB + (uint32_t)(bi) * BUFBYTES;                         \
        CP16(_ba + doff[0], Ah + (size_t)(m0 + row_l) * Dsz + _k0 + c8);       \
        CP16(_ba + doff[1], Ah + (size_t)(m0 + 64 + row_l) * Dsz + _k0 + c8);  \
        CP16(_bb + doff[0], Bh + (size_t)(n0 + row_l) * Dsz + _k0 + c8);       \
        CP16(_bb + doff[1], Bh + (size_t)(n0 + 64 + row_l) * Dsz + _k0 + c8);  \
        CP_COMMIT();                                                            \
    } while (0)

    G_ISSUE(0, 0);
    G_ISSUE(1, 1);
    G_ISSUE(2, 2);

    int bi = 0, ii = 3;
    for (int s = 0; s < NS; s++) {
        if (s + 2 < NS) CP_WAIT2(); else if (s + 1 < NS) CP_WAIT1(); else CP_WAIT0();
        __syncthreads();
        if (s + 3 < NS) {
            G_ISSUE(s + 3, ii);
            ii = (ii + 1) & 3;
        }
        uint32_t bufA = sA + (uint32_t)bi * BUFBYTES;
        uint32_t bufB = sB + (uint32_t)bi * BUFBYTES;
        bi = (bi + 1) & 3;
#pragma unroll
        for (int ks = 0; ks < 2; ks++) {
            int cb = ks * 2 + (lane >> 4);
            uint32_t am[2][4], bm[4][4];
            int rA0 = wm * 32 + (lane & 15);
#pragma unroll
            for (int mi = 0; mi < 2; mi++) {
                int r = rA0 + mi * 16;
                ldsm4(am[mi], bufA + (uint32_t)(r * 64 + ((cb ^ ((r >> 1) & 3)) << 4)));
            }
#pragma unroll
            for (int nb = 0; nb < 4; nb++) {
                int r = wn * 64 + nb * 16 + (lane & 15);
                ldsm4(bm[nb], bufB + (uint32_t)(r * 64 + ((cb ^ ((r >> 1) & 3)) << 4)));
            }
#pragma unroll
            for (int mi = 0; mi < 2; mi++)
#pragma unroll
                for (int nb = 0; nb < 4; nb++) {
                    mma16816(&acc[(mi * 8 + nb * 2 + 0) * 4], am[mi], bm[nb][0], bm[nb][2]);
                    mma16816(&acc[(mi * 8 + nb * 2 + 1) * 4], am[mi], bm[nb][1], bm[nb][3]);
                }
        }
    }

    // epilogue
    const int l4 = lane >> 2, lm = lane & 3;
    __half* dsth = (mode == 0) ? g_Qh : g_Kh;
#pragma unroll
    for (int mi = 0; mi < 2; mi++)
#pragma unroll
        for (int nb = 0; nb < 4; nb++)
#pragma unroll
            for (int j = 0; j < 2; j++)
#pragma unroll
                for (int rh = 0; rh < 2; rh++) {
                    float v0 = acc[(mi * 8 + nb * 2 + j) * 4 + rh * 2 + 0];
                    float v1 = acc[(mi * 8 + nb * 2 + j) * 4 + rh * 2 + 1];
                    int row = m0 + wm * 32 + mi * 16 + l4 + rh * 8;
                    int col = n0 + wn * 64 + nb * 16 + j * 8 + lm * 2;
                    size_t idx = ((size_t)row << 11) + col;
                    if (mode <= 1) {
                        int p = (col & 127) >> 1, srow = row & (Ssz - 1);
                        float cc = rc[srow * 64 + p], sn = rs[srow * 64 + p];
                        float re = v0 * cc - v1 * sn, im = v0 * sn + v1 * cc;
                        *(__half2*)(dsth + idx) = __floats2half2_rn(re, im);
                    } else if (mode == 2) {
                        *(__half2*)(g_Vh + idx) = __floats2half2_rn(v0, v1);
                    } else {
                        *(float2*)(Co + idx) = make_float2(v0 * AINV, v1 * AINV);
                    }
                }
}

// ---------------- LSE + w + scaled wV fused; persistent-Q fp16, 4-stage K ring ----------------
// smem: [0,32768) Q persistent; [32768,65536) K ring 4x8KB;
//       [65536,66048) diag; [66048,67072) tmp; [67072,67584) wrow
#define L_SMEM 67584

__global__ __launch_bounds__(256) void lse_mma() {
    extern __shared__ __align__(16) char smem[];
    const uint32_t sQ = smem_u32(smem);
    const uint32_t sK = sQ + 32768u;
    float* diag = (float*)(smem + 65536);
    float* tmp  = (float*)(smem + 66048);
    float* wrow = (float*)(smem + 67072);
    const int tid = threadIdx.x, w = tid >> 5, lane = tid & 31;
    const int wm = w & 3, wn = w >> 2;
    const int q0 = blockIdx.x * 128, h = blockIdx.y, b = blockIdx.z;
    const float scale = 0.08838834764831845f;
    const size_t qbase = (((size_t)(b * Ssz + q0)) << 11) + h * DHsz;
    const size_t kbb   = (((size_t)(b * Ssz)) << 11) + h * DHsz;
    const int row_l = tid >> 2, cch = tid & 3, c8 = cch * 8;
    uint32_t doff[2];
#pragma unroll
    for (int t = 0; t < 2; t++) {
        int r = t * 64 + row_l;
        doff[t] = (uint32_t)(r * 64 + ((cch ^ ((r >> 1) & 3)) << 4));
    }

    // persistent Q: 128 rows x 128 cols fp16 = 2048 16B chunks
#pragma unroll
    for (int i = 0; i < 8; i++) {
        int u = tid + i * 256;
        int r = u >> 4, ch = u & 15;
        CP16(sQ + (uint32_t)(r * 256 + ((ch ^ (r & 7)) << 4)),
             g_Qh + qbase + ((size_t)r << 11) + ch * 8);
    }
    CP_COMMIT();

    const int NS = 64;   // 16 chunks x 4 dh-slabs
#define L_ISSUE(st, bix) do {                                                  \
        int _c = (st) >> 2, _dh0 = ((st) & 3) << 5;                           \
        size_t _kb = kbb + ((size_t)(_c * 128) << 11) + _dh0;                 \
        uint32_t _bk = sK + (uint32_t)(bix) * BUFBYTES;                       \
        CP16(_bk + doff[0], g_Kh + _kb + ((size_t)row_l << 11) + c8);         \
        CP16(_bk + doff[1], g_Kh + _kb + ((size_t)(64 + row_l) << 11) + c8);  \
        CP_COMMIT();                                                           \
    } while (0)

    L_ISSUE(0, 0);
    L_ISSUE(1, 1);
    L_ISSUE(2, 2);

    float acc[64];
#pragma unroll
    for (int i = 0; i < 64; i++) acc[i] = 0.f;
    float rsacc[4] = {0.f, 0.f, 0.f, 0.f};
    const int l4 = lane >> 2, lm = lane & 3;

    int bi = 0, ii = 3, j = 0, cnum = 0;
    for (int s = 0; s < NS; s++) {
        if (s + 2 < NS) CP_WAIT2(); else if (s + 1 < NS) CP_WAIT1(); else CP_WAIT0();
        __syncthreads();
        if (s + 3 < NS) {
            L_ISSUE(s + 3, ii);
            ii = (ii + 1) & 3;
        }
        uint32_t bufK = sK + (uint32_t)bi * BUFBYTES;
        bi = (bi + 1) & 3;
        int qchb = (j & 3) * 4;
#pragma unroll
        for (int ks = 0; ks < 2; ks++) {
            int cb = ks * 2 + (lane >> 4);
            uint32_t am[2][4], bm[4][4];
            int rA0 = wm * 32 + (lane & 15);
#pragma unroll
            for (int mi = 0; mi < 2; mi++) {
                int r = rA0 + mi * 16;
                int ch = qchb + cb;
                ldsm4(am[mi], sQ + (uint32_t)(r * 256 + ((ch ^ (r & 7)) << 4)));
            }
#pragma unroll
            for (int nb = 0; nb < 4; nb++) {
                int r = wn * 64 + nb * 16 + (lane & 15);
                ldsm4(bm[nb], bufK + (uint32_t)(r * 64 + ((cb ^ ((r >> 1) & 3)) << 4)));
            }
#pragma unroll
            for (int mi = 0; mi < 2; mi++)
#pragma unroll
                for (int nb = 0; nb < 4; nb++) {
                    mma16816(&acc[(mi * 8 + nb * 2 + 0) * 4], am[mi], bm[nb][0], bm[nb][2]);
                    mma16816(&acc[(mi * 8 + nb * 2 + 1) * 4], am[mi], bm[nb][1], bm[nb][3]);
                }
        }
        if (++j == 4) {   // key chunk complete
            j = 0;
#pragma unroll
            for (int mi = 0; mi < 2; mi++)
#pragma unroll
                for (int rh = 0; rh < 2; rh++) {
                    float pp = 0.f;
#pragma unroll
                    for (int nb = 0; nb < 4; nb++)
#pragma unroll
                        for (int jj = 0; jj < 2; jj++) {
                            pp += __expf(acc[(mi * 8 + nb * 2 + jj) * 4 + rh * 2 + 0] * scale);
                            pp += __expf(acc[(mi * 8 + nb * 2 + jj) * 4 + rh * 2 + 1] * scale);
                        }
                    rsacc[mi * 2 + rh] += pp;
                }
            if (cnum == (int)blockIdx.x) {   // diagonal chunk
#pragma unroll
                for (int mi = 0; mi < 2; mi++)
#pragma unroll
                    for (int nb = 0; nb < 4; nb++)
#pragma unroll
                        for (int jj = 0; jj < 2; jj++)
#pragma unroll
                            for (int rh = 0; rh < 2; rh++) {
                                int row = wm * 32 + mi * 16 + l4 + rh * 8;
                                int col = wn * 64 + nb * 16 + jj * 8 + lm * 2;
                                if (row == col)
                                    diag[row] = acc[(mi * 8 + nb * 2 + jj) * 4 + rh * 2 + 0];
                                if (row == col + 1)
                                    diag[row] = acc[(mi * 8 + nb * 2 + jj) * 4 + rh * 2 + 1];
                            }
            }
            cnum++;
#pragma unroll
            for (int i = 0; i < 64; i++) acc[i] = 0.f;
        }
    }

    // rowsum reduce -> w in smem
#pragma unroll
    for (int i = 0; i < 4; i++) {
        rsacc[i] += __shfl_xor_sync(0xffffffffu, rsacc[i], 1);
        rsacc[i] += __shfl_xor_sync(0xffffffffu, rsacc[i], 2);
    }
    if (lm == 0) {
#pragma unroll
        for (int mi = 0; mi < 2; mi++)
#pragma unroll
            for (int rh = 0; rh < 2; rh++)
                tmp[wn * 128 + wm * 32 + mi * 16 + rh * 8 + l4] = rsacc[mi * 2 + rh];
    }
    __syncthreads();
    if (tid < 128) {
        float sum = tmp[tid] + tmp[128 + tid];
        wrow[tid] = __expf(diag[tid] * scale - logf(sum)) * ASCALE;
    }
    __syncthreads();

    // fused scaled wV: A[q0..q0+127, h*128..+127] = 1024 * w * V (fp16 in, fp16 out)
#pragma unroll
    for (int i = 0; i < 8; i++) {
        int u = tid + i * 256;          // 0..2047
        int r = u >> 4, ch = u & 15;
        size_t idx = (((size_t)(b * Ssz + q0 + r)) << 11) + h * DHsz + ch * 8;
        float wv = wrow[r];
        __half2 vin[4];
        *(uint4*)vin = *(const uint4*)(g_Vh + idx);
        __half2 vout[4];
#pragma unroll
        for (int q = 0; q < 4; q++) {
            float2 f = __half22float2(vin[q]);
            vout[q] = __floats2half2_rn(f.x * wv, f.y * wv);
        }
        *(uint4*)(g_Ah + idx) = *(uint4*)vout;
    }
}

// ---------------- launch ----------------
extern "C" void kernel_launch(void* const* d_in, const int* in_sizes, int n_in,
                              void* d_out, int out_size) {
    const float* x  = (const float*)d_in[0];
    const float* rc = (const float*)d_in[1];
    const float* rs = (const float*)d_in[2];
    const float* W[4] = { (const float*)d_in[3], (const float*)d_in[4],
                          (const float*)d_in[5], (const float*)d_in[6] };
    float* out = (float*)d_out;

    cudaFuncSetAttribute(gemm_mma, cudaFuncAttributeMaxDynamicSharedMemorySize, G_SMEM);
    cudaFuncSetAttribute(lse_mma, cudaFuncAttributeMaxDynamicSharedMemorySize, L_SMEM);

    dim3 gg(Msz / 128, Dsz / 128);          // (32, 16)
    const int wgrid = Dsz * Dsz / 4 / 256;  // 4096

    half_kernel<<<(Msz * Dsz / 4 + 255) / 256, 256>>>(x, 4, Msz * Dsz / 4);   // 1
    half_kernel<<<wgrid, 256>>>(W[0], 0, Dsz * Dsz / 4);                      // 2
    gemm_mma<<<gg, 256, G_SMEM>>>(rc, rs, nullptr, 0, 0);                     // 3: Q + rope
    half_kernel<<<wgrid, 256>>>(W[1], 1, Dsz * Dsz / 4);                      // 4
    gemm_mma<<<gg, 256, G_SMEM>>>(rc, rs, nullptr, 1, 1);                     // 5: K + rope
    half_kernel<<<wgrid, 256>>>(W[2], 2, Dsz * Dsz / 4);                      // 6
    gemm_mma<<<gg, 256, G_SMEM>>>(rc, rs, nullptr, 2, 2);                     // 7: V
    lse_mma<<<dim3(Ssz / 128, Hn, Bsz), 256, L_SMEM>>>();                     // 8: lse+w+A
    half_kernel<<<wgrid, 256>>>(W[3], 3, Dsz * Dsz / 4);                      // 9
    gemm_mma<<<gg, 256, G_SMEM>>>(rc, rs, out, 3, 3);                         // 10: A@Wo^T /1024
}

// round 10
// speedup vs baseline: 3.2938x; 1.0756x over previous
#include <cuda_runtime.h>
#include <cuda_fp16.h>
#include <cstdint>

#define Bsz 2
#define Ssz 2048
#define Dsz 2048
#define Hn 16
#define DHsz 128
#define Msz (Bsz*Ssz)

__device__ __align__(16) __half g_xh[(size_t)Msz*Dsz];
__device__ __align__(16) __half g_Wh[4][(size_t)Dsz*Dsz];
__device__ __align__(16) __half g_Qh[(size_t)Msz*Dsz];
__device__ __align__(16) __half g_Kh[(size_t)Msz*Dsz];
__device__ __align__(16) __half g_Vh[(size_t)Msz*Dsz];
__device__ __align__(16) __half g_Ah[(size_t)Msz*Dsz];   // 1024 * w * V

#define ASCALE 1024.0f
#define AINV   0.0009765625f

__device__ __forceinline__ uint32_t smem_u32(const void* p) {
    uint32_t a;
    asm("{ .reg .u64 t; cvta.to.shared.u64 t, %1; cvt.u32.u64 %0, t; }" : "=r"(a) : "l"(p));
    return a;
}
__device__ __forceinline__ void ldsm4(uint32_t* r, uint32_t a) {
    asm volatile("ldmatrix.sync.aligned.m8n8.x4.shared.b16 {%0,%1,%2,%3}, [%4];"
                 : "=r"(r[0]), "=r"(r[1]), "=r"(r[2]), "=r"(r[3]) : "r"(a));
}
__device__ __forceinline__ void mma16816(float* c, const uint32_t* a, uint32_t b0, uint32_t b1) {
    asm volatile("mma.sync.aligned.m16n8k16.row.col.f32.f16.f16.f32 "
                 "{%0,%1,%2,%3},{%4,%5,%6,%7},{%8,%9},{%0,%1,%2,%3};"
                 : "+f"(c[0]), "+f"(c[1]), "+f"(c[2]), "+f"(c[3])
                 : "r"(a[0]), "r"(a[1]), "r"(a[2]), "r"(a[3]), "r"(b0), "r"(b1));
}
#define CP16(dst, src) asm volatile("cp.async.cg.shared.global [%0], [%1], 16;" :: "r"(dst), "l"(src))
#define CP_COMMIT()    asm volatile("cp.async.commit_group;" ::: "memory")
#define CP_WAIT2()     asm volatile("cp.async.wait_group 2;" ::: "memory")
#define CP_WAIT1()     asm volatile("cp.async.wait_group 1;" ::: "memory")
#define CP_WAIT0()     asm volatile("cp.async.wait_group 0;" ::: "memory")

// ---------------- single fused fp32 -> fp16 conversion (x + all 4 W) ----------------
// 25.2M floats, 8 per thread: 3145728 threads = 12288 blocks x 256
#define XCHUNKS 1048576   // Msz*Dsz/8
#define WCHUNKS 524288    // Dsz*Dsz/8

__global__ __launch_bounds__(256) void conv_all(const float* __restrict__ x,
                                                const float* __restrict__ w0,
                                                const float* __restrict__ w1,
                                                const float* __restrict__ w2,
                                                const float* __restrict__ w3) {
    int i = blockIdx.x * 256 + threadIdx.x;
    const float* src;
    __half* dst;
    size_t off;
    if (i < XCHUNKS) {
        src = x; dst = g_xh; off = (size_t)i * 8;
    } else {
        int r = i - XCHUNKS;
        int sel = r >> 19;            // /524288
        off = (size_t)(r & (WCHUNKS - 1)) * 8;
        src = (sel == 0) ? w0 : (sel == 1) ? w1 : (sel == 2) ? w2 : w3;
        dst = g_Wh[sel];
    }
    float4 v0 = *(const float4*)(src + off);
    float4 v1 = *(const float4*)(src + off + 4);
    __half2 h[4];
    h[0] = __floats2half2_rn(v0.x, v0.y);
    h[1] = __floats2half2_rn(v0.z, v0.w);
    h[2] = __floats2half2_rn(v1.x, v1.y);
    h[3] = __floats2half2_rn(v1.z, v1.w);
    *(uint4*)(dst + off) = *(uint4*)h;
}

// ---------------- GEMM: 1-pass fp16, 4-stage cp.async ----------------
// mode 0: merged QKV projections, grid (32, 48); by>>4 selects Wq/Wk/Wv
// mode 3: out = (1024 w V) @ Wo^T / 1024, grid (32, 16)
#define BUFBYTES 8192u
#define G_SMEM 65536

__global__ __launch_bounds__(256) void gemm_mma(const float* __restrict__ rc,
                                                const float* __restrict__ rs,
                                                float* __restrict__ Co, int mode) {
    extern __shared__ __align__(16) char smem[];
    const int tid = threadIdx.x, w = tid >> 5, lane = tid & 31;
    const int wm = w & 3, wn = w >> 2;
    const int m0 = blockIdx.x * 128;
    const int wsel = (mode == 3) ? 3 : (blockIdx.y >> 4);
    const int n0 = (mode == 3) ? blockIdx.y * 128 : (blockIdx.y & 15) * 128;
    const __half* Ah = (mode == 3) ? g_Ah : g_xh;
    const __half* Bh = g_Wh[wsel];

    float acc[64];
#pragma unroll
    for (int i = 0; i < 64; i++) acc[i] = 0.f;

    const int row_l = tid >> 2, cch = tid & 3, c8 = cch * 8;
    uint32_t doff[2];
#pragma unroll
    for (int t = 0; t < 2; t++) {
        int r = t * 64 + row_l;
        doff[t] = (uint32_t)(r * 64 + ((cch ^ ((r >> 1) & 3)) << 4));
    }
    const uint32_t sA = smem_u32(smem), sB = sA + 32768u;
    const int NS = 64;

#define G_ISSUE(st, bi) do {                                                   \
        int _k0 = (st) << 5;                                                   \
        uint32_t _ba = sA + (uint32_t)(bi) * BUFBYTES;                         \
        uint32_t _bb = sB + (uint32_t)(bi) * BUFBYTES;                         \
        CP16(_ba + doff[0], Ah + (size_t)(m0 + row_l) * Dsz + _k0 + c8);       \
        CP16(_ba + doff[1], Ah + (size_t)(m0 + 64 + row_l) * Dsz + _k0 + c8);  \
        CP16(_bb + doff[0], Bh + (size_t)(n0 + row_l) * Dsz + _k0 + c8);       \
        CP16(_bb + doff[1], Bh + (size_t)(n0 + 64 + row_l) * Dsz + _k0 + c8);  \
        CP_COMMIT();                                                            \
    } while (0)

    G_ISSUE(0, 0);
    G_ISSUE(1, 1);
    G_ISSUE(2, 2);

    int bi = 0, ii = 3;
    for (int s = 0; s < NS; s++) {
        if (s + 2 < NS) CP_WAIT2(); else if (s + 1 < NS) CP_WAIT1(); else CP_WAIT0();
        __syncthreads();
        if (s + 3 < NS) {
            G_ISSUE(s + 3, ii);
            ii = (ii + 1) & 3;
        }
        uint32_t bufA = sA + (uint32_t)bi * BUFBYTES;
        uint32_t bufB = sB + (uint32_t)bi * BUFBYTES;
        bi = (bi + 1) & 3;
#pragma unroll
        for (int ks = 0; ks < 2; ks++) {
            int cb = ks * 2 + (lane >> 4);
            uint32_t am[2][4], bm[4][4];
            int rA0 = wm * 32 + (lane & 15);
#pragma unroll
            for (int mi = 0; mi < 2; mi++) {
                int r = rA0 + mi * 16;
                ldsm4(am[mi], bufA + (uint32_t)(r * 64 + ((cb ^ ((r >> 1) & 3)) << 4)));
            }
#pragma unroll
            for (int nb = 0; nb < 4; nb++) {
                int r = wn * 64 + nb * 16 + (lane & 15);
                ldsm4(bm[nb], bufB + (uint32_t)(r * 64 + ((cb ^ ((r >> 1) & 3)) << 4)));
            }
#pragma unroll
            for (int mi = 0; mi < 2; mi++)
#pragma unroll
                for (int nb = 0; nb < 4; nb++) {
                    mma16816(&acc[(mi * 8 + nb * 2 + 0) * 4], am[mi], bm[nb][0], bm[nb][2]);
                    mma16816(&acc[(mi * 8 + nb * 2 + 1) * 4], am[mi], bm[nb][1], bm[nb][3]);
                }
        }
    }

    // epilogue
    const int l4 = lane >> 2, lm = lane & 3;
    __half* dsth = (wsel == 0) ? g_Qh : (wsel == 1) ? g_Kh : g_Vh;
#pragma unroll
    for (int mi = 0; mi < 2; mi++)
#pragma unroll
        for (int nb = 0; nb < 4; nb++)
#pragma unroll
            for (int j = 0; j < 2; j++)
#pragma unroll
                for (int rh = 0; rh < 2; rh++) {
                    float v0 = acc[(mi * 8 + nb * 2 + j) * 4 + rh * 2 + 0];
                    float v1 = acc[(mi * 8 + nb * 2 + j) * 4 + rh * 2 + 1];
                    int row = m0 + wm * 32 + mi * 16 + l4 + rh * 8;
                    int col = n0 + wn * 64 + nb * 16 + j * 8 + lm * 2;
                    size_t idx = ((size_t)row << 11) + col;
                    if (mode == 3) {
                        *(float2*)(Co + idx) = make_float2(v0 * AINV, v1 * AINV);
                    } else if (wsel <= 1) {
                        int p = (col & 127) >> 1, srow = row & (Ssz - 1);
                        float cc = rc[srow * 64 + p], sn = rs[srow * 64 + p];
                        float re = v0 * cc - v1 * sn, im = v0 * sn + v1 * cc;
                        *(__half2*)(dsth + idx) = __floats2half2_rn(re, im);
                    } else {
                        *(__half2*)(g_Vh + idx) = __floats2half2_rn(v0, v1);
                    }
                }
}

// ---------------- LSE + w + scaled wV fused; persistent-Q fp16, 4-stage K ring ----------------
// smem: [0,32768) Q persistent; [32768,65536) K ring 4x8KB;
//       [65536,66048) diag; [66048,67072) tmp; [67072,67584) wrow
#define L_SMEM 67584

__global__ __launch_bounds__(256) void lse_mma() {
    extern __shared__ __align__(16) char smem[];
    const uint32_t sQ = smem_u32(smem);
    const uint32_t sK = sQ + 32768u;
    float* diag = (float*)(smem + 65536);
    float* tmp  = (float*)(smem + 66048);
    float* wrow = (float*)(smem + 67072);
    const int tid = threadIdx.x, w = tid >> 5, lane = tid & 31;
    const int wm = w & 3, wn = w >> 2;
    const int q0 = blockIdx.x * 128, h = blockIdx.y, b = blockIdx.z;
    const float scale = 0.08838834764831845f;
    const size_t qbase = (((size_t)(b * Ssz + q0)) << 11) + h * DHsz;
    const size_t kbb   = (((size_t)(b * Ssz)) << 11) + h * DHsz;
    const int row_l = tid >> 2, cch = tid & 3, c8 = cch * 8;
    uint32_t doff[2];
#pragma unroll
    for (int t = 0; t < 2; t++) {
        int r = t * 64 + row_l;
        doff[t] = (uint32_t)(r * 64 + ((cch ^ ((r >> 1) & 3)) << 4));
    }

    // persistent Q: 128 rows x 128 cols fp16 = 2048 16B chunks
#pragma unroll
    for (int i = 0; i < 8; i++) {
        int u = tid + i * 256;
        int r = u >> 4, ch = u & 15;
        CP16(sQ + (uint32_t)(r * 256 + ((ch ^ (r & 7)) << 4)),
             g_Qh + qbase + ((size_t)r << 11) + ch * 8);
    }
    CP_COMMIT();

    const int NS = 64;   // 16 chunks x 4 dh-slabs
#define L_ISSUE(st, bix) do {                                                  \
        int _c = (st) >> 2, _dh0 = ((st) & 3) << 5;                           \
        size_t _kb = kbb + ((size_t)(_c * 128) << 11) + _dh0;                 \
        uint32_t _bk = sK + (uint32_t)(bix) * BUFBYTES;                       \
        CP16(_bk + doff[0], g_Kh + _kb + ((size_t)row_l << 11) + c8);         \
        CP16(_bk + doff[1], g_Kh + _kb + ((size_t)(64 + row_l) << 11) + c8);  \
        CP_COMMIT();                                                           \
    } while (0)

    L_ISSUE(0, 0);
    L_ISSUE(1, 1);
    L_ISSUE(2, 2);

    float acc[64];
#pragma unroll
    for (int i = 0; i < 64; i++) acc[i] = 0.f;
    float rsacc[4] = {0.f, 0.f, 0.f, 0.f};
    const int l4 = lane >> 2, lm = lane & 3;

    int bi = 0, ii = 3, j = 0, cnum = 0;
    for (int s = 0; s < NS; s++) {
        if (s + 2 < NS) CP_WAIT2(); else if (s + 1 < NS) CP_WAIT1(); else CP_WAIT0();
        __syncthreads();
        if (s + 3 < NS) {
            L_ISSUE(s + 3, ii);
            ii = (ii + 1) & 3;
        }
        uint32_t bufK = sK + (uint32_t)bi * BUFBYTES;
        bi = (bi + 1) & 3;
        int qchb = (j & 3) * 4;
#pragma unroll
        for (int ks = 0; ks < 2; ks++) {
            int cb = ks * 2 + (lane >> 4);
            uint32_t am[2][4], bm[4][4];
            int rA0 = wm * 32 + (lane & 15);
#pragma unroll
            for (int mi = 0; mi < 2; mi++) {
                int r = rA0 + mi * 16;
                int ch = qchb + cb;
                ldsm4(am[mi], sQ + (uint32_t)(r * 256 + ((ch ^ (r & 7)) << 4)));
            }
#pragma unroll
            for (int nb = 0; nb < 4; nb++) {
                int r = wn * 64 + nb * 16 + (lane & 15);
                ldsm4(bm[nb], bufK + (uint32_t)(r * 64 + ((cb ^ ((r >> 1) & 3)) << 4)));
            }
#pragma unroll
            for (int mi = 0; mi < 2; mi++)
#pragma unroll
                for (int nb = 0; nb < 4; nb++) {
                    mma16816(&acc[(mi * 8 + nb * 2 + 0) * 4], am[mi], bm[nb][0], bm[nb][2]);
                    mma16816(&acc[(mi * 8 + nb * 2 + 1) * 4], am[mi], bm[nb][1], bm[nb][3]);
                }
        }
        if (++j == 4) {   // key chunk complete
            j = 0;
#pragma unroll
            for (int mi = 0; mi < 2; mi++)
#pragma unroll
                for (int rh = 0; rh < 2; rh++) {
                    float pp = 0.f;
#pragma unroll
                    for (int nb = 0; nb < 4; nb++)
#pragma unroll
                        for (int jj = 0; jj < 2; jj++) {
                            pp += __expf(acc[(mi * 8 + nb * 2 + jj) * 4 + rh * 2 + 0] * scale);
                            pp += __expf(acc[(mi * 8 + nb * 2 + jj) * 4 + rh * 2 + 1] * scale);
                        }
                    rsacc[mi * 2 + rh] += pp;
                }
            if (cnum == (int)blockIdx.x) {   // diagonal chunk
#pragma unroll
                for (int mi = 0; mi < 2; mi++)
#pragma unroll
                    for (int nb = 0; nb < 4; nb++)
#pragma unroll
                        for (int jj = 0; jj < 2; jj++)
#pragma unroll
                            for (int rh = 0; rh < 2; rh++) {
                                int row = wm * 32 + mi * 16 + l4 + rh * 8;
                                int col = wn * 64 + nb * 16 + jj * 8 + lm * 2;
                                if (row == col)
                                    diag[row] = acc[(mi * 8 + nb * 2 + jj) * 4 + rh * 2 + 0];
                                if (row == col + 1)
                                    diag[row] = acc[(mi * 8 + nb * 2 + jj) * 4 + rh * 2 + 1];
                            }
            }
            cnum++;
#pragma unroll
            for (int i = 0; i < 64; i++) acc[i] = 0.f;
        }
    }

    // rowsum reduce -> w in smem
#pragma unroll
    for (int i = 0; i < 4; i++) {
        rsacc[i] += __shfl_xor_sync(0xffffffffu, rsacc[i], 1);
        rsacc[i] += __shfl_xor_sync(0xffffffffu, rsacc[i], 2);
    }
    if (lm == 0) {
#pragma unroll
        for (int mi = 0; mi < 2; mi++)
#pragma unroll
            for (int rh = 0; rh < 2; rh++)
                tmp[wn * 128 + wm * 32 + mi * 16 + rh * 8 + l4] = rsacc[mi * 2 + rh];
    }
    __syncthreads();
    if (tid < 128) {
        float sum = tmp[tid] + tmp[128 + tid];
        wrow[tid] = __expf(diag[tid] * scale - logf(sum)) * ASCALE;
    }
    __syncthreads();

    // fused scaled wV: A[q0..q0+127, h*128..+127] = 1024 * w * V (fp16 in, fp16 out)
#pragma unroll
    for (int i = 0; i < 8; i++) {
        int u = tid + i * 256;          // 0..2047
        int r = u >> 4, ch = u & 15;
        size_t idx = (((size_t)(b * Ssz + q0 + r)) << 11) + h * DHsz + ch * 8;
        float wv = wrow[r];
        __half2 vin[4];
        *(uint4*)vin = *(const uint4*)(g_Vh + idx);
        __half2 vout[4];
#pragma unroll
        for (int q = 0; q < 4; q++) {
            float2 f = __half22float2(vin[q]);
            vout[q] = __floats2half2_rn(f.x * wv, f.y * wv);
        }
        *(uint4*)(g_Ah + idx) = *(uint4*)vout;
    }
}

// ---------------- launch ----------------
extern "C" void kernel_launch(void* const* d_in, const int* in_sizes, int n_in,
                              void* d_out, int out_size) {
    const float* x  = (const float*)d_in[0];
    const float* rc = (const float*)d_in[1];
    const float* rs = (const float*)d_in[2];
    const float* Wq = (const float*)d_in[3];
    const float* Wk = (const float*)d_in[4];
    const float* Wv = (const float*)d_in[5];
    const float* Wo = (const float*)d_in[6];
    float* out = (float*)d_out;

    cudaFuncSetAttribute(gemm_mma, cudaFuncAttributeMaxDynamicSharedMemorySize, G_SMEM);
    cudaFuncSetAttribute(lse_mma, cudaFuncAttributeMaxDynamicSharedMemorySize, L_SMEM);

    conv_all<<<(XCHUNKS + 4 * WCHUNKS) / 256, 256>>>(x, Wq, Wk, Wv, Wo);      // 1: all fp16
    gemm_mma<<<dim3(Msz / 128, 48), 256, G_SMEM>>>(rc, rs, nullptr, 0);       // 2: QKV merged
    lse_mma<<<dim3(Ssz / 128, Hn, Bsz), 256, L_SMEM>>>();                     // 3: lse+w+A
    gemm_mma<<<dim3(Msz / 128, Dsz / 128), 256, G_SMEM>>>(rc, rs, out, 3);    // 4: A@Wo^T
}

// round 11
// speedup vs baseline: 3.5908x; 1.0902x over previous
#include <cuda_runtime.h>
#include <cuda_fp16.h>
#include <cstdint>

#define Bsz 2
#define Ssz 2048
#define Dsz 2048
#define Hn 16
#define DHsz 128
#define Msz (Bsz*Ssz)

__device__ __align__(16) __half g_xh[(size_t)Msz*Dsz];
__device__ __align__(16) __half g_Wh[4][(size_t)Dsz*Dsz];
__device__ __align__(16) __half g_Qh[(size_t)Msz*Dsz];
__device__ __align__(16) __half g_Kh[(size_t)Msz*Dsz];
__device__ __align__(16) __half g_Vh[(size_t)Msz*Dsz];
__device__ __align__(16) __half g_Ah[(size_t)Msz*Dsz];   // 1024 * w * V

#define ASCALE 1024.0f
#define AINV   0.0009765625f

__device__ __forceinline__ uint32_t smem_u32(const void* p) {
    uint32_t a;
    asm("{ .reg .u64 t; cvta.to.shared.u64 t, %1; cvt.u32.u64 %0, t; }" : "=r"(a) : "l"(p));
    return a;
}
__device__ __forceinline__ void ldsm4(uint32_t* r, uint32_t a) {
    asm volatile("ldmatrix.sync.aligned.m8n8.x4.shared.b16 {%0,%1,%2,%3}, [%4];"
                 : "=r"(r[0]), "=r"(r[1]), "=r"(r[2]), "=r"(r[3]) : "r"(a));
}
__device__ __forceinline__ void mma16816(float* c, const uint32_t* a, uint32_t b0, uint32_t b1) {
    asm volatile("mma.sync.aligned.m16n8k16.row.col.f32.f16.f16.f32 "
                 "{%0,%1,%2,%3},{%4,%5,%6,%7},{%8,%9},{%0,%1,%2,%3};"
                 : "+f"(c[0]), "+f"(c[1]), "+f"(c[2]), "+f"(c[3])
                 : "r"(a[0]), "r"(a[1]), "r"(a[2]), "r"(a[3]), "r"(b0), "r"(b1));
}
#define CP16(dst, src) asm volatile("cp.async.cg.shared.global [%0], [%1], 16;" :: "r"(dst), "l"(src))
#define CP_COMMIT()    asm volatile("cp.async.commit_group;" ::: "memory")
#define CP_WAIT1()     asm volatile("cp.async.wait_group 1;" ::: "memory")
#define CP_WAIT0()     asm volatile("cp.async.wait_group 0;" ::: "memory")

// ---------------- single fused fp32 -> fp16 conversion (x + all 4 W) ----------------
#define XCHUNKS 1048576   // Msz*Dsz/8
#define WCHUNKS 524288    // Dsz*Dsz/8

__global__ __launch_bounds__(256) void conv_all(const float* __restrict__ x,
                                                const float* __restrict__ w0,
                                                const float* __restrict__ w1,
                                                const float* __restrict__ w2,
                                                const float* __restrict__ w3) {
    int i = blockIdx.x * 256 + threadIdx.x;
    const float* src;
    __half* dst;
    size_t off;
    if (i < XCHUNKS) {
        src = x; dst = g_xh; off = (size_t)i * 8;
    } else {
        int r = i - XCHUNKS;
        int sel = r >> 19;
        off = (size_t)(r & (WCHUNKS - 1)) * 8;
        src = (sel == 0) ? w0 : (sel == 1) ? w1 : (sel == 2) ? w2 : w3;
        dst = g_Wh[sel];
    }
    float4 v0 = *(const float4*)(src + off);
    float4 v1 = *(const float4*)(src + off + 4);
    __half2 h[4];
    h[0] = __floats2half2_rn(v0.x, v0.y);
    h[1] = __floats2half2_rn(v0.z, v0.w);
    h[2] = __floats2half2_rn(v1.x, v1.y);
    h[3] = __floats2half2_rn(v1.z, v1.w);
    *(uint4*)(dst + off) = *(uint4*)h;
}

// ---------------- GEMM: 1-pass fp16, K=64 slabs, 3-stage cp.async (16KB bufs) ----------------
// mode 0: merged QKV projections, grid (32, 48); by>>4 selects Wq/Wk/Wv
// mode 3: out = (1024 w V) @ Wo^T / 1024, grid (32, 16)
#define KBUF 16384u
#define G_SMEM 98304      // 3 stages x (16KB A + 16KB B)

__global__ __launch_bounds__(256, 2) void gemm_mma(const float* __restrict__ rc,
                                                   const float* __restrict__ rs,
                                                   float* __restrict__ Co, int mode) {
    extern __shared__ __align__(16) char smem[];
    const int tid = threadIdx.x, w = tid >> 5, lane = tid & 31;
    const int wm = w & 3, wn = w >> 2;
    const int m0 = blockIdx.x * 128;
    const int wsel = (mode == 3) ? 3 : (blockIdx.y >> 4);
    const int n0 = (mode == 3) ? blockIdx.y * 128 : (blockIdx.y & 15) * 128;
    const __half* Ah = (mode == 3) ? g_Ah : g_xh;
    const __half* Bh = g_Wh[wsel];

    float acc[64];
#pragma unroll
    for (int i = 0; i < 64; i++) acc[i] = 0.f;

    const uint32_t sA = smem_u32(smem), sB = sA + 3 * KBUF;
    // loader: 1024 16B-chunks per 16KB buffer, 4 per thread (rows of 128B, 8 chunks/row)
    uint32_t doff[4];
    int lrow[4], lch[4];
#pragma unroll
    for (int i = 0; i < 4; i++) {
        int u = tid + (i << 8);
        lrow[i] = u >> 3; lch[i] = u & 7;
        doff[i] = (uint32_t)(lrow[i] * 128 + ((lch[i] ^ (lrow[i] & 7)) << 4));
    }
    const int NS = 32;

#define G_ISSUE(st, bi) do {                                                        \
        int _k0 = (st) << 6;                                                        \
        uint32_t _ba = sA + (uint32_t)(bi) * KBUF;                                  \
        uint32_t _bb = sB + (uint32_t)(bi) * KBUF;                                  \
        _Pragma("unroll")                                                           \
        for (int _i = 0; _i < 4; _i++) {                                            \
            CP16(_ba + doff[_i], Ah + (size_t)(m0 + lrow[_i]) * Dsz + _k0 + lch[_i] * 8); \
            CP16(_bb + doff[_i], Bh + (size_t)(n0 + lrow[_i]) * Dsz + _k0 + lch[_i] * 8); \
        }                                                                           \
        CP_COMMIT();                                                                 \
    } while (0)

    G_ISSUE(0, 0);
    G_ISSUE(1, 1);

    int bi = 0, ii = 2;
    for (int s = 0; s < NS; s++) {
        if (s + 1 < NS) CP_WAIT1(); else CP_WAIT0();
        __syncthreads();
        if (s + 2 < NS) {
            G_ISSUE(s + 2, ii);
            ii = (ii == 2) ? 0 : ii + 1;
        }
        uint32_t bufA = sA + (uint32_t)bi * KBUF;
        uint32_t bufB = sB + (uint32_t)bi * KBUF;
        bi = (bi == 2) ? 0 : bi + 1;
#pragma unroll
        for (int ks = 0; ks < 4; ks++) {
            int cb = ks * 2 + (lane >> 4);
            uint32_t am[2][4], bm[4][4];
            int rA0 = wm * 32 + (lane & 15);
#pragma unroll
            for (int mi = 0; mi < 2; mi++) {
                int r = rA0 + mi * 16;
                ldsm4(am[mi], bufA + (uint32_t)(r * 128 + ((cb ^ (r & 7)) << 4)));
            }
#pragma unroll
            for (int nb = 0; nb < 4; nb++) {
                int r = wn * 64 + nb * 16 + (lane & 15);
                ldsm4(bm[nb], bufB + (uint32_t)(r * 128 + ((cb ^ (r & 7)) << 4)));
            }
#pragma unroll
            for (int mi = 0; mi < 2; mi++)
#pragma unroll
                for (int nb = 0; nb < 4; nb++) {
                    mma16816(&acc[(mi * 8 + nb * 2 + 0) * 4], am[mi], bm[nb][0], bm[nb][2]);
                    mma16816(&acc[(mi * 8 + nb * 2 + 1) * 4], am[mi], bm[nb][1], bm[nb][3]);
                }
        }
    }

    // epilogue
    const int l4 = lane >> 2, lm = lane & 3;
    __half* dsth = (wsel == 0) ? g_Qh : (wsel == 1) ? g_Kh : g_Vh;
#pragma unroll
    for (int mi = 0; mi < 2; mi++)
#pragma unroll
        for (int nb = 0; nb < 4; nb++)
#pragma unroll
            for (int j = 0; j < 2; j++)
#pragma unroll
                for (int rh = 0; rh < 2; rh++) {
                    float v0 = acc[(mi * 8 + nb * 2 + j) * 4 + rh * 2 + 0];
                    float v1 = acc[(mi * 8 + nb * 2 + j) * 4 + rh * 2 + 1];
                    int row = m0 + wm * 32 + mi * 16 + l4 + rh * 8;
                    int col = n0 + wn * 64 + nb * 16 + j * 8 + lm * 2;
                    size_t idx = ((size_t)row << 11) + col;
                    if (mode == 3) {
                        *(float2*)(Co + idx) = make_float2(v0 * AINV, v1 * AINV);
                    } else if (wsel <= 1) {
                        int p = (col & 127) >> 1, srow = row & (Ssz - 1);
                        float cc = rc[srow * 64 + p], sn = rs[srow * 64 + p];
                        float re = v0 * cc - v1 * sn, im = v0 * sn + v1 * cc;
                        *(__half2*)(dsth + idx) = __floats2half2_rn(re, im);
                    } else {
                        *(__half2*)(g_Vh + idx) = __floats2half2_rn(v0, v1);
                    }
                }
}

// ---------------- LSE + w + scaled wV fused; persistent-Q, K=64 slabs ----------------
// smem: [0,32768) Q persistent (rows 256B, 16 chunks, swizzle ch^(r&7));
//       [32768,81920) K ring 3x16KB; [81920,82432) diag; [82432,83456) tmp; [83456,83968) wrow
#define L_SMEM 83968

__global__ __launch_bounds__(256, 2) void lse_mma() {
    extern __shared__ __align__(16) char smem[];
    const uint32_t sQ = smem_u32(smem);
    const uint32_t sK = sQ + 32768u;
    float* diag = (float*)(smem + 81920);
    float* tmp  = (float*)(smem + 82432);
    float* wrow = (float*)(smem + 83456);
    const int tid = threadIdx.x, w = tid >> 5, lane = tid & 31;
    const int wm = w & 3, wn = w >> 2;
    const int q0 = blockIdx.x * 128, h = blockIdx.y, b = blockIdx.z;
    const float scale = 0.08838834764831845f;
    const size_t qbase = (((size_t)(b * Ssz + q0)) << 11) + h * DHsz;
    const size_t kbb   = (((size_t)(b * Ssz)) << 11) + h * DHsz;

    uint32_t doff[4];
    int lrow[4], lch[4];
#pragma unroll
    for (int i = 0; i < 4; i++) {
        int u = tid + (i << 8);
        lrow[i] = u >> 3; lch[i] = u & 7;
        doff[i] = (uint32_t)(lrow[i] * 128 + ((lch[i] ^ (lrow[i] & 7)) << 4));
    }

    // persistent Q: 128 rows x 128 cols fp16 = 2048 16B chunks (rows 256B/16 chunks)
#pragma unroll
    for (int i = 0; i < 8; i++) {
        int u = tid + i * 256;
        int r = u >> 4, ch = u & 15;
        CP16(sQ + (uint32_t)(r * 256 + ((ch ^ (r & 7)) << 4)),
             g_Qh + qbase + ((size_t)r << 11) + ch * 8);
    }
    CP_COMMIT();

    const int NS = 32;   // 16 key chunks x 2 dh-slabs (64 each)
#define L_ISSUE(st, bix) do {                                                       \
        int _c = (st) >> 1, _dh0 = ((st) & 1) << 6;                                \
        uint32_t _bk = sK + (uint32_t)(bix) * KBUF;                                \
        _Pragma("unroll")                                                          \
        for (int _i = 0; _i < 4; _i++)                                             \
            CP16(_bk + doff[_i],                                                   \
                 g_Kh + kbb + ((size_t)(_c * 128 + lrow[_i]) << 11) + _dh0 + lch[_i] * 8); \
        CP_COMMIT();                                                                \
    } while (0)

    L_ISSUE(0, 0);
    L_ISSUE(1, 1);

    float acc[64];
#pragma unroll
    for (int i = 0; i < 64; i++) acc[i] = 0.f;
    float rsacc[4] = {0.f, 0.f, 0.f, 0.f};
    const int l4 = lane >> 2, lm = lane & 3;

    int bi = 0, ii = 2, j = 0, cnum = 0;
    for (int s = 0; s < NS; s++) {
        if (s + 1 < NS) CP_WAIT1(); else CP_WAIT0();
        __syncthreads();
        if (s + 2 < NS) {
            L_ISSUE(s + 2, ii);
            ii = (ii == 2) ? 0 : ii + 1;
        }
        uint32_t bufK = sK + (uint32_t)bi * KBUF;
        bi = (bi == 2) ? 0 : bi + 1;
#pragma unroll
        for (int ks = 0; ks < 4; ks++) {
            int cb = ks * 2 + (lane >> 4);
            int qch = j * 8 + cb;            // j = dh-slab (0/1), 8 chunks per 64-dh half
            uint32_t am[2][4], bm[4][4];
            int rA0 = wm * 32 + (lane & 15);
#pragma unroll
            for (int mi = 0; mi < 2; mi++) {
                int r = rA0 + mi * 16;
                ldsm4(am[mi], sQ + (uint32_t)(r * 256 + ((qch ^ (r & 7)) << 4)));
            }
#pragma unroll
            for (int nb = 0; nb < 4; nb++) {
                int r = wn * 64 + nb * 16 + (lane & 15);
                ldsm4(bm[nb], bufK + (uint32_t)(r * 128 + ((cb ^ (r & 7)) << 4)));
            }
#pragma unroll
            for (int mi = 0; mi < 2; mi++)
#pragma unroll
                for (int nb = 0; nb < 4; nb++) {
                    mma16816(&acc[(mi * 8 + nb * 2 + 0) * 4], am[mi], bm[nb][0], bm[nb][2]);
                    mma16816(&acc[(mi * 8 + nb * 2 + 1) * 4], am[mi], bm[nb][1], bm[nb][3]);
                }
        }
        if (++j == 2) {   // key chunk complete
            j = 0;
#pragma unroll
            for (int mi = 0; mi < 2; mi++)
#pragma unroll
                for (int rh = 0; rh < 2; rh++) {
                    float pp = 0.f;
#pragma unroll
                    for (int nb = 0; nb < 4; nb++)
#pragma unroll
                        for (int jj = 0; jj < 2; jj++) {
                            pp += __expf(acc[(mi * 8 + nb * 2 + jj) * 4 + rh * 2 + 0] * scale);
                            pp += __expf(acc[(mi * 8 + nb * 2 + jj) * 4 + rh * 2 + 1] * scale);
                        }
                    rsacc[mi * 2 + rh] += pp;
                }
            if (cnum == (int)blockIdx.x) {   // diagonal chunk
#pragma unroll
                for (int mi = 0; mi < 2; mi++)
#pragma unroll
                    for (int nb = 0; nb < 4; nb++)
#pragma unroll
                        for (int jj = 0; jj < 2; jj++)
#pragma unroll
                            for (int rh = 0; rh < 2; rh++) {
                                int row = wm * 32 + mi * 16 + l4 + rh * 8;
                                int col = wn * 64 + nb * 16 + jj * 8 + lm * 2;
                                if (row == col)
                                    diag[row] = acc[(mi * 8 + nb * 2 + jj) * 4 + rh * 2 + 0];
                                if (row == col + 1)
                                    diag[row] = acc[(mi * 8 + nb * 2 + jj) * 4 + rh * 2 + 1];
                            }
            }
            cnum++;
#pragma unroll
            for (int i = 0; i < 64; i++) acc[i] = 0.f;
        }
    }

    // rowsum reduce -> w in smem
#pragma unroll
    for (int i = 0; i < 4; i++) {
        rsacc[i] += __shfl_xor_sync(0xffffffffu, rsacc[i], 1);
        rsacc[i] += __shfl_xor_sync(0xffffffffu, rsacc[i], 2);
    }
    if (lm == 0) {
#pragma unroll
        for (int mi = 0; mi < 2; mi++)
#pragma unroll
            for (int rh = 0; rh < 2; rh++)
                tmp[wn * 128 + wm * 32 + mi * 16 + rh * 8 + l4] = rsacc[mi * 2 + rh];
    }
    __syncthreads();
    if (tid < 128) {
        float sum = tmp[tid] + tmp[128 + tid];
        wrow[tid] = __expf(diag[tid] * scale - logf(sum)) * ASCALE;
    }
    __syncthreads();

    // fused scaled wV: A[q0..q0+127, h*128..+127] = 1024 * w * V
#pragma unroll
    for (int i = 0; i < 8; i++) {
        int u = tid + i * 256;
        int r = u >> 4, ch = u & 15;
        size_t idx = (((size_t)(b * Ssz + q0 + r)) << 11) + h * DHsz + ch * 8;
        float wv = wrow[r];
        __half2 vin[4];
        *(uint4*)vin = *(const uint4*)(g_Vh + idx);
        __half2 vout[4];
#pragma unroll
        for (int q = 0; q < 4; q++) {
            float2 f = __half22float2(vin[q]);
            vout[q] = __floats2half2_rn(f.x * wv, f.y * wv);
        }
        *(uint4*)(g_Ah + idx) = *(uint4*)vout;
    }
}

// ---------------- launch ----------------
extern "C" void kernel_launch(void* const* d_in, const int* in_sizes, int n_in,
                              void* d_out, int out_size) {
    const float* x  = (const float*)d_in[0];
    const float* rc = (const float*)d_in[1];
    const float* rs = (const float*)d_in[2];
    const float* Wq = (const float*)d_in[3];
    const float* Wk = (const float*)d_in[4];
    const float* Wv = (const float*)d_in[5];
    const float* Wo = (const float*)d_in[6];
    float* out = (float*)d_out;

    cudaFuncSetAttribute(gemm_mma, cudaFuncAttributeMaxDynamicSharedMemorySize, G_SMEM);
    cudaFuncSetAttribute(lse_mma, cudaFuncAttributeMaxDynamicSharedMemorySize, L_SMEM);

    conv_all<<<(XCHUNKS + 4 * WCHUNKS) / 256, 256>>>(x, Wq, Wk, Wv, Wo);      // 1
    gemm_mma<<<dim3(Msz / 128, 48), 256, G_SMEM>>>(rc, rs, nullptr, 0);       // 2: QKV merged
    lse_mma<<<dim3(Ssz / 128, Hn, Bsz), 256, L_SMEM>>>();                     // 3: lse+w+A
    gemm_mma<<<dim3(Msz / 128, Dsz / 128), 256, G_SMEM>>>(rc, rs, out, 3);    // 4: A@Wo^T
}

// round 12
// speedup vs baseline: 3.7001x; 1.0304x over previous
#include <cuda_runtime.h>
#include <cuda_fp16.h>
#include <cstdint>

#define Bsz 2
#define Ssz 2048
#define Dsz 2048
#define Hn 16
#define DHsz 128
#define Msz (Bsz*Ssz)

__device__ __align__(16) __half g_xh[(size_t)Msz*Dsz];
__device__ __align__(16) __half g_Wh[4][(size_t)Dsz*Dsz];
__device__ __align__(16) __half g_Qh[(size_t)Msz*Dsz];
__device__ __align__(16) __half g_Kh[(size_t)Msz*Dsz];
__device__ __align__(16) __half g_Vh[(size_t)Msz*Dsz];
__device__ __align__(16) __half g_Ah[(size_t)Msz*Dsz];   // 1024 * w * V

#define ASCALE 1024.0f
#define AINV   0.0009765625f

__device__ __forceinline__ uint32_t smem_u32(const void* p) {
    uint32_t a;
    asm("{ .reg .u64 t; cvta.to.shared.u64 t, %1; cvt.u32.u64 %0, t; }" : "=r"(a) : "l"(p));
    return a;
}
__device__ __forceinline__ void ldsm4(uint32_t* r, uint32_t a) {
    asm volatile("ldmatrix.sync.aligned.m8n8.x4.shared.b16 {%0,%1,%2,%3}, [%4];"
                 : "=r"(r[0]), "=r"(r[1]), "=r"(r[2]), "=r"(r[3]) : "r"(a));
}
__device__ __forceinline__ void mma16816(float* c, const uint32_t* a, uint32_t b0, uint32_t b1) {
    asm volatile("mma.sync.aligned.m16n8k16.row.col.f32.f16.f16.f32 "
                 "{%0,%1,%2,%3},{%4,%5,%6,%7},{%8,%9},{%0,%1,%2,%3};"
                 : "+f"(c[0]), "+f"(c[1]), "+f"(c[2]), "+f"(c[3])
                 : "r"(a[0]), "r"(a[1]), "r"(a[2]), "r"(a[3]), "r"(b0), "r"(b1));
}
#define CP16(dst, src) asm volatile("cp.async.cg.shared.global [%0], [%1], 16;" :: "r"(dst), "l"(src))
#define CP_COMMIT()    asm volatile("cp.async.commit_group;" ::: "memory")
#define CP_WAIT1()     asm volatile("cp.async.wait_group 1;" ::: "memory")
#define CP_WAIT0()     asm volatile("cp.async.wait_group 0;" ::: "memory")

// ---------------- single fused fp32 -> fp16 conversion (x + all 4 W) ----------------
#define XCHUNKS 1048576   // Msz*Dsz/8
#define WCHUNKS 524288    // Dsz*Dsz/8

__global__ __launch_bounds__(256) void conv_all(const float* __restrict__ x,
                                                const float* __restrict__ w0,
                                                const float* __restrict__ w1,
                                                const float* __restrict__ w2,
                                                const float* __restrict__ w3) {
    int i = blockIdx.x * 256 + threadIdx.x;
    const float* src;
    __half* dst;
    size_t off;
    if (i < XCHUNKS) {
        src = x; dst = g_xh; off = (size_t)i * 8;
    } else {
        int r = i - XCHUNKS;
        int sel = r >> 19;
        off = (size_t)(r & (WCHUNKS - 1)) * 8;
        src = (sel == 0) ? w0 : (sel == 1) ? w1 : (sel == 2) ? w2 : w3;
        dst = g_Wh[sel];
    }
    float4 v0 = *(const float4*)(src + off);
    float4 v1 = *(const float4*)(src + off + 4);
    __half2 h[4];
    h[0] = __floats2half2_rn(v0.x, v0.y);
    h[1] = __floats2half2_rn(v0.z, v0.w);
    h[2] = __floats2half2_rn(v1.x, v1.y);
    h[3] = __floats2half2_rn(v1.z, v1.w);
    *(uint4*)(dst + off) = *(uint4*)h;
}

// ---------------- GEMM: 1-pass fp16, K=64 slabs, 3-stage cp.async ----------------
// mode 0: merged QKV projections, grid (32, 48); by>>4 selects Wq/Wk/Wv
// mode 3: out = (1024 w V) @ Wo^T / 1024, grid (32, 16)
#define KBUF 16384u
#define G_SMEM 98304

__global__ __launch_bounds__(256, 2) void gemm_mma(const float* __restrict__ rc,
                                                   const float* __restrict__ rs,
                                                   float* __restrict__ Co, int mode) {
    extern __shared__ __align__(16) char smem[];
    const int tid = threadIdx.x, w = tid >> 5, lane = tid & 31;
    const int wm = w & 3, wn = w >> 2;
    const int m0 = blockIdx.x * 128;
    const int wsel = (mode == 3) ? 3 : (blockIdx.y >> 4);
    const int n0 = (mode == 3) ? blockIdx.y * 128 : (blockIdx.y & 15) * 128;
    const __half* Ah = (mode == 3) ? g_Ah : g_xh;
    const __half* Bh = g_Wh[wsel];

    float acc[64];
#pragma unroll
    for (int i = 0; i < 64; i++) acc[i] = 0.f;

    const uint32_t sA = smem_u32(smem), sB = sA + 3 * KBUF;
    // loader: 4 chunks/thread, pointer-incremented global addresses
    uint32_t doff[4];
    const __half* pA[4];
    const __half* pB[4];
#pragma unroll
    for (int i = 0; i < 4; i++) {
        int u = tid + (i << 8);
        int r = u >> 3, ch = u & 7;
        doff[i] = (uint32_t)(r * 128 + ((ch ^ (r & 7)) << 4));
        pA[i] = Ah + (size_t)(m0 + r) * Dsz + ch * 8;
        pB[i] = Bh + (size_t)(n0 + r) * Dsz + ch * 8;
    }
    // ldsm loop-invariant bases (XOR-foldable: bits 4-6 only get flipped)
    const uint32_t lanehi4 = (uint32_t)((lane >> 4) << 4);
    uint32_t baseA[2], baseB[4];
    {
        int rA0 = wm * 32 + (lane & 15);
#pragma unroll
        for (int mi = 0; mi < 2; mi++) {
            int r = rA0 + mi * 16;
            baseA[mi] = (uint32_t)(r * 128 + ((r & 7) << 4));
        }
#pragma unroll
        for (int nb = 0; nb < 4; nb++) {
            int r = wn * 64 + nb * 16 + (lane & 15);
            baseB[nb] = (uint32_t)(r * 128 + ((r & 7) << 4));
        }
    }
    const int NS = 32;

#define G_ISSUE(bi) do {                                                       \
        uint32_t _ba = sA + (uint32_t)(bi) * KBUF;                             \
        uint32_t _bb = sB + (uint32_t)(bi) * KBUF;                             \
        _Pragma("unroll")                                                      \
        for (int _i = 0; _i < 4; _i++) {                                       \
            CP16(_ba + doff[_i], pA[_i]);                                      \
            CP16(_bb + doff[_i], pB[_i]);                                      \
            pA[_i] += 64; pB[_i] += 64;                                        \
        }                                                                      \
        CP_COMMIT();                                                            \
    } while (0)

    G_ISSUE(0);
    G_ISSUE(1);

    int bi = 0, ii = 2;
    for (int s = 0; s < NS; s++) {
        if (s + 1 < NS) CP_WAIT1(); else CP_WAIT0();
        __syncthreads();
        if (s + 2 < NS) {
            G_ISSUE(ii);
            ii = (ii == 2) ? 0 : ii + 1;
        }
        uint32_t bufA = sA + (uint32_t)bi * KBUF;
        uint32_t bufB = sB + (uint32_t)bi * KBUF;
        bi = (bi == 2) ? 0 : bi + 1;
#pragma unroll
        for (int ks = 0; ks < 4; ks++) {
            uint32_t cbx = (uint32_t)(ks << 5) | lanehi4;
            uint32_t am[2][4], bm[4][4];
#pragma unroll
            for (int mi = 0; mi < 2; mi++)
                ldsm4(am[mi], bufA + (baseA[mi] ^ cbx));
#pragma unroll
            for (int nb = 0; nb < 4; nb++)
                ldsm4(bm[nb], bufB + (baseB[nb] ^ cbx));
#pragma unroll
            for (int mi = 0; mi < 2; mi++)
#pragma unroll
                for (int nb = 0; nb < 4; nb++) {
                    mma16816(&acc[(mi * 8 + nb * 2 + 0) * 4], am[mi], bm[nb][0], bm[nb][2]);
                    mma16816(&acc[(mi * 8 + nb * 2 + 1) * 4], am[mi], bm[nb][1], bm[nb][3]);
                }
        }
    }

    // epilogue
    const int l4 = lane >> 2, lm = lane & 3;
    __half* dsth = (wsel == 0) ? g_Qh : (wsel == 1) ? g_Kh : g_Vh;
#pragma unroll
    for (int mi = 0; mi < 2; mi++)
#pragma unroll
        for (int nb = 0; nb < 4; nb++)
#pragma unroll
            for (int j = 0; j < 2; j++)
#pragma unroll
                for (int rh = 0; rh < 2; rh++) {
                    float v0 = acc[(mi * 8 + nb * 2 + j) * 4 + rh * 2 + 0];
                    float v1 = acc[(mi * 8 + nb * 2 + j) * 4 + rh * 2 + 1];
                    int row = m0 + wm * 32 + mi * 16 + l4 + rh * 8;
                    int col = n0 + wn * 64 + nb * 16 + j * 8 + lm * 2;
                    size_t idx = ((size_t)row << 11) + col;
                    if (mode == 3) {
                        *(float2*)(Co + idx) = make_float2(v0 * AINV, v1 * AINV);
                    } else if (wsel <= 1) {
                        int p = (col & 127) >> 1, srow = row & (Ssz - 1);
                        float cc = rc[srow * 64 + p], sn = rs[srow * 64 + p];
                        float re = v0 * cc - v1 * sn, im = v0 * sn + v1 * cc;
                        *(__half2*)(dsth + idx) = __floats2half2_rn(re, im);
                    } else {
                        *(__half2*)(g_Vh + idx) = __floats2half2_rn(v0, v1);
                    }
                }
}

// ---------------- LSE + w + scaled wV fused; persistent-Q, K=64 slabs ----------------
// smem: [0,32768) Q persistent (rows 256B, swizzle ch^(r&7));
//       [32768,81920) K ring 3x16KB; [81920,82432) diag; [82432,83456) tmp; [83456,83968) wrow
#define L_SMEM 83968

__global__ __launch_bounds__(256, 2) void lse_mma() {
    extern __shared__ __align__(16) char smem[];
    const uint32_t sQ = smem_u32(smem);
    const uint32_t sK = sQ + 32768u;
    float* diag = (float*)(smem + 81920);
    float* tmp  = (float*)(smem + 82432);
    float* wrow = (float*)(smem + 83456);
    const int tid = threadIdx.x, w = tid >> 5, lane = tid & 31;
    const int wm = w & 3, wn = w >> 2;
    const int q0 = blockIdx.x * 128, h = blockIdx.y, b = blockIdx.z;
    const float scale = 0.08838834764831845f;
    const size_t qbase = (((size_t)(b * Ssz + q0)) << 11) + h * DHsz;
    const size_t kbb   = (((size_t)(b * Ssz)) << 11) + h * DHsz;

    uint32_t doff[4];
    const __half* pK[4];
#pragma unroll
    for (int i = 0; i < 4; i++) {
        int u = tid + (i << 8);
        int r = u >> 3, ch = u & 7;
        doff[i] = (uint32_t)(r * 128 + ((ch ^ (r & 7)) << 4));
        pK[i] = g_Kh + kbb + ((size_t)r << 11) + ch * 8;
    }

    // persistent Q: 128 rows x 128 cols fp16 (rows 256B/16 chunks)
#pragma unroll
    for (int i = 0; i < 8; i++) {
        int u = tid + i * 256;
        int r = u >> 4, ch = u & 15;
        CP16(sQ + (uint32_t)(r * 256 + ((ch ^ (r & 7)) << 4)),
             g_Qh + qbase + ((size_t)r << 11) + ch * 8);
    }
    CP_COMMIT();

    const uint32_t lanehi4 = (uint32_t)((lane >> 4) << 4);
    uint32_t baseQ[2], baseK[4];
    {
        int rA0 = wm * 32 + (lane & 15);
#pragma unroll
        for (int mi = 0; mi < 2; mi++) {
            int r = rA0 + mi * 16;
            baseQ[mi] = (uint32_t)(r * 256 + ((r & 7) << 4));   // bit 7 free for j
        }
#pragma unroll
        for (int nb = 0; nb < 4; nb++) {
            int r = wn * 64 + nb * 16 + (lane & 15);
            baseK[nb] = (uint32_t)(r * 128 + ((r & 7) << 4));
        }
    }

    const int NS = 32;   // 16 key chunks x 2 dh-slabs (64 each)
    // pointer advance: even stage -> +64 (dh half), odd -> next chunk -64
#define L_ISSUE(bix, par) do {                                                 \
        uint32_t _bk = sK + (uint32_t)(bix) * KBUF;                            \
        size_t _adv = (par) ? (size_t)(128 * 2048 - 64) : (size_t)64;          \
        _Pragma("unroll")                                                      \
        for (int _i = 0; _i < 4; _i++) {                                       \
            CP16(_bk + doff[_i], pK[_i]);                                      \
            pK[_i] += _adv;                                                    \
        }                                                                      \
        CP_COMMIT();                                                            \
    } while (0)

    L_ISSUE(0, 0);
    L_ISSUE(1, 1);

    float acc[64];
#pragma unroll
    for (int i = 0; i < 64; i++) acc[i] = 0.f;
    float rsacc[4] = {0.f, 0.f, 0.f, 0.f};
    const int l4 = lane >> 2, lm = lane & 3;

    int bi = 0, ii = 2, j = 0, cnum = 0;
    for (int s = 0; s < NS; s++) {
        if (s + 1 < NS) CP_WAIT1(); else CP_WAIT0();
        __syncthreads();
        if (s + 2 < NS) {
            L_ISSUE(ii, s & 1);   // stage s+2 has same parity as s
            ii = (ii == 2) ? 0 : ii + 1;
        }
        uint32_t bufK = sK + (uint32_t)bi * KBUF;
        bi = (bi == 2) ? 0 : bi + 1;
        const uint32_t jbit = (uint32_t)(j << 7);
#pragma unroll
        for (int ks = 0; ks < 4; ks++) {
            uint32_t cbx = (uint32_t)(ks << 5) | lanehi4;
            uint32_t qx  = cbx | jbit;
            uint32_t am[2][4], bm[4][4];
#pragma unroll
            for (int mi = 0; mi < 2; mi++)
                ldsm4(am[mi], sQ + (baseQ[mi] ^ qx));
#pragma unroll
            for (int nb = 0; nb < 4; nb++)
                ldsm4(bm[nb], bufK + (baseK[nb] ^ cbx));
#pragma unroll
            for (int mi = 0; mi < 2; mi++)
#pragma unroll
                for (int nb = 0; nb < 4; nb++) {
                    mma16816(&acc[(mi * 8 + nb * 2 + 0) * 4], am[mi], bm[nb][0], bm[nb][2]);
                    mma16816(&acc[(mi * 8 + nb * 2 + 1) * 4], am[mi], bm[nb][1], bm[nb][3]);
                }
        }
        if (++j == 2) {   // key chunk complete
            j = 0;
#pragma unroll
            for (int mi = 0; mi < 2; mi++)
#pragma unroll
                for (int rh = 0; rh < 2; rh++) {
                    float pp = 0.f;
#pragma unroll
                    for (int nb = 0; nb < 4; nb++)
#pragma unroll
                        for (int jj = 0; jj < 2; jj++) {
                            pp += __expf(acc[(mi * 8 + nb * 2 + jj) * 4 + rh * 2 + 0] * scale);
                            pp += __expf(acc[(mi * 8 + nb * 2 + jj) * 4 + rh * 2 + 1] * scale);
                        }
                    rsacc[mi * 2 + rh] += pp;
                }
            if (cnum == (int)blockIdx.x) {   // diagonal chunk
#pragma unroll
                for (int mi = 0; mi < 2; mi++)
#pragma unroll
                    for (int nb = 0; nb < 4; nb++)
#pragma unroll
                        for (int jj = 0; jj < 2; jj++)
#pragma unroll
                            for (int rh = 0; rh < 2; rh++) {
                                int row = wm * 32 + mi * 16 + l4 + rh * 8;
                                int col = wn * 64 + nb * 16 + jj * 8 + lm * 2;
                                if (row == col)
                                    diag[row] = acc[(mi * 8 + nb * 2 + jj) * 4 + rh * 2 + 0];
                                if (row == col + 1)
                                    diag[row] = acc[(mi * 8 + nb * 2 + jj) * 4 + rh * 2 + 1];
                            }
            }
            cnum++;
#pragma unroll
            for (int i = 0; i < 64; i++) acc[i] = 0.f;
        }
    }

    // rowsum reduce -> w in smem
#pragma unroll
    for (int i = 0; i < 4; i++) {
        rsacc[i] += __shfl_xor_sync(0xffffffffu, rsacc[i], 1);
        rsacc[i] += __shfl_xor_sync(0xffffffffu, rsacc[i], 2);
    }
    if (lm == 0) {
#pragma unroll
        for (int mi = 0; mi < 2; mi++)
#pragma unroll
            for (int rh = 0; rh < 2; rh++)
                tmp[wn * 128 + wm * 32 + mi * 16 + rh * 8 + l4] = rsacc[mi * 2 + rh];
    }
    __syncthreads();
    if (tid < 128) {
        float sum = tmp[tid] + tmp[128 + tid];
        wrow[tid] = __expf(diag[tid] * scale - logf(sum)) * ASCALE;
    }
    __syncthreads();

    // fused scaled wV: A[q0..q0+127, h*128..+127] = 1024 * w * V
#pragma unroll
    for (int i = 0; i < 8; i++) {
        int u = tid + i * 256;
        int r = u >> 4, ch = u & 15;
        size_t idx = (((size_t)(b * Ssz + q0 + r)) << 11) + h * DHsz + ch * 8;
        float wv = wrow[r];
        __half2 vin[4];
        *(uint4*)vin = *(const uint4*)(g_Vh + idx);
        __half2 vout[4];
#pragma unroll
        for (int q = 0; q < 4; q++) {
            float2 f = __half22float2(vin[q]);
            vout[q] = __floats2half2_rn(f.x * wv, f.y * wv);
        }
        *(uint4*)(g_Ah + idx) = *(uint4*)vout;
    }
}

// ---------------- launch ----------------
extern "C" void kernel_launch(void* const* d_in, const int* in_sizes, int n_in,
                              void* d_out, int out_size) {
    const float* x  = (const float*)d_in[0];
    const float* rc = (const float*)d_in[1];
    const float* rs = (const float*)d_in[2];
    const float* Wq = (const float*)d_in[3];
    const float* Wk = (const float*)d_in[4];
    const float* Wv = (const float*)d_in[5];
    const float* Wo = (const float*)d_in[6];
    float* out = (float*)d_out;

    cudaFuncSetAttribute(gemm_mma, cudaFuncAttributeMaxDynamicSharedMemorySize, G_SMEM);
    cudaFuncSetAttribute(lse_mma, cudaFuncAttributeMaxDynamicSharedMemorySize, L_SMEM);

    conv_all<<<(XCHUNKS + 4 * WCHUNKS) / 256, 256>>>(x, Wq, Wk, Wv, Wo);      // 1
    gemm_mma<<<dim3(Msz / 128, 48), 256, G_SMEM>>>(rc, rs, nullptr, 0);       // 2: QKV merged
    lse_mma<<<dim3(Ssz / 128, Hn, Bsz), 256, L_SMEM>>>();                     // 3: lse+w+A
    gemm_mma<<<dim3(Msz / 128, Dsz / 128), 256, G_SMEM>>>(rc, rs, out, 3);    // 4: A@Wo^T
}